// round 13
// baseline (speedup 1.0000x reference)
#include <cuda_runtime.h>
#include <cuda_fp16.h>
#include <cstdint>
#include <cstddef>

#define NTOK 8192
#define LSEQ 2048
#define DMODEL 512
#define DFF 1365
#define DFFP 1376
#define NWG  2730   // 2*DFF interleaved

// weight-plane offsets (fp16 elements)
#define OFF_INST 0
#define CNT_INST (512 * 768)
#define OFF_QKV  (OFF_INST + CNT_INST)
#define CNT_QKV  (3 * 1536 * 512)
#define OFF_OUT  (OFF_QKV + CNT_QKV)
#define CNT_OUT  (3 * 512 * 512)
#define OFF_WG   (OFF_OUT + CNT_OUT)
#define CNT_WG   (3 * NWG * 512)
#define OFF_W2   (OFF_WG + CNT_WG)
#define CNT_W2   (3 * 512 * DFFP)
#define WTOT     (OFF_W2 + CNT_W2)

#define WSCALE   64.0f
#define WUNSCALE 0.015625f

// ---------------- scratch (device globals; allocation-free) ----------------
__device__ __align__(16) uint16_t g_cat_hi[NTOK * 768];
__device__ __align__(16) uint16_t g_cat_lo[NTOK * 768];
__device__ __align__(16) float    g_h[NTOK * 512];
__device__ __align__(16) uint16_t g_xn_hi[NTOK * 512];
__device__ __align__(16) uint16_t g_xn_lo[NTOK * 512];
__device__ __align__(16) float    g_qkv[NTOK * 1536];
__device__ __align__(16) uint16_t g_att_hi[NTOK * 512];
__device__ __align__(16) uint16_t g_att_lo[NTOK * 512];
__device__ __align__(16) uint16_t g_u_hi[NTOK * DFFP];    // pads stay 0 (static zero init)
__device__ __align__(16) uint16_t g_u_lo[NTOK * DFFP];
__device__ __align__(16) float    g_w2p[3 * 512 * DFFP];
__device__ __align__(16) uint16_t g_whi[WTOT];
__device__ __align__(16) uint16_t g_wlo[WTOT];
__device__ __align__(16) float    g_bg[3 * NWG];
__device__ __align__(16) float    g_ropec[LSEQ * 32];
__device__ __align__(16) float    g_ropes[LSEQ * 32];
__device__ int g_is64;

// ---------------- helpers ----------------
__device__ __forceinline__ uint32_t smem_u32(const void* p) {
    uint32_t a;
    asm("{ .reg .u64 t; cvta.to.shared.u64 t, %1; cvt.u32.u64 %0, t; }" : "=r"(a) : "l"(p));
    return a;
}
__device__ __forceinline__ void split2h(float x, uint16_t& h, uint16_t& l) {
    __half hh = __float2half_rn(x);
    __half ll = __float2half_rn(x - __half2float(hh));
    h = __half_as_ushort(hh);
    l = __half_as_ushort(ll);
}
__device__ __forceinline__ void mma_f16(float* d, const uint32_t* a, uint32_t b0, uint32_t b1) {
    asm volatile(
        "mma.sync.aligned.m16n8k16.row.col.f32.f16.f16.f32 "
        "{%0,%1,%2,%3}, {%4,%5,%6,%7}, {%8,%9}, {%0,%1,%2,%3};"
        : "+f"(d[0]), "+f"(d[1]), "+f"(d[2]), "+f"(d[3])
        : "r"(a[0]), "r"(a[1]), "r"(a[2]), "r"(a[3]), "r"(b0), "r"(b1));
}
__device__ __forceinline__ void cpasync16(uint32_t dst, const void* src) {
    asm volatile("cp.async.cg.shared.global [%0], [%1], 16;" :: "r"(dst), "l"(src) : "memory");
}

// ---------------- dtype probe for x (int64 vs int32) ----------------
__global__ void detect_k(const int* x) {
    long long s = 0;
    for (int i = 1; i < 8192; i += 2) { int v = x[i]; s += (v < 0) ? -(long long)v : (long long)v; }
    g_is64 = (s == 0) ? 1 : 0;
}

// ---------------- rope tables ----------------
__global__ void ropetab_k(float* rc, float* rs) {
    int p = blockIdx.x, d2 = threadIdx.x;
    float inv = expf((float)d2 * -0.28782313662425572f);
    float sn, cs;
    sincosf((float)p * inv, &sn, &cs);
    rc[p * 32 + d2] = cs;
    rs[p * 32 + d2] = sn;
}

// ---------------- split weights (scaled by 64) into fp16 hi/lo planes ----------------
__global__ void splitw_k(const float* __restrict__ src, uint16_t* __restrict__ hi,
                         uint16_t* __restrict__ lo, int n)
{
    int stride = gridDim.x * 256;
    for (int i = blockIdx.x * 256 + threadIdx.x; i < n; i += stride) {
        uint16_t h, l;
        split2h(src[i] * WSCALE, h, l);
        hi[i] = h; lo[i] = l;
    }
}

// ---------------- interleave w1/w3 rows (2j -> w1_j, 2j+1 -> w3_j), split ----------------
__global__ void splitwg_k(const float* __restrict__ w1, const float* __restrict__ w3,
                          uint16_t* __restrict__ hi, uint16_t* __restrict__ lo)
{
    int stride = gridDim.x * 256;
    for (int i = blockIdx.x * 256 + threadIdx.x; i < CNT_WG; i += stride) {
        int k = i & 511, row = i >> 9;
        int l = row / NWG, r = row - l * NWG, j = r >> 1;
        const float* src = (r & 1) ? w3 : w1;
        float val = src[((size_t)l * DFF + j) * 512 + k] * WSCALE;
        uint16_t h, lw;
        split2h(val, h, lw);
        hi[i] = h; lo[i] = lw;
    }
}

__global__ void bgbuild_k(const float* __restrict__ b1, const float* __restrict__ b3,
                          float* __restrict__ bg)
{
    int i = blockIdx.x * 256 + threadIdx.x;
    if (i < 3 * NWG) {
        int l = i / NWG, r = i - l * NWG, j = r >> 1;
        bg[i] = ((r & 1) ? b3 : b1)[l * DFF + j];
    }
}

// ---------------- pad w2 (3,512,1365) -> (3,512,1376) ----------------
__global__ void padw2_k(const float* __restrict__ w2, float* __restrict__ o)
{
    int row = blockIdx.x;  // 0..1535
    const float* src = w2 + (size_t)row * DFF;
    float* dst = o + (size_t)row * DFFP;
    for (int k = threadIdx.x; k < DFFP; k += 256) dst[k] = (k < DFF) ? src[k] : 0.f;
}

// ---------------- embed + input projections + silu (split output) ----------------
__global__ __launch_bounds__(192) void embed_k(
    const void* __restrict__ xraw,
    const float* __restrict__ emb,
    const float* __restrict__ reg_w, const float* __restrict__ reg_b,
    const float* __restrict__ br_w,  const float* __restrict__ br_b,
    const float* __restrict__ sh_w,  const float* __restrict__ sh_b,
    uint16_t* __restrict__ chi, uint16_t* __restrict__ clo)
{
    int m = blockIdx.x;
    int t = threadIdx.x;
    __shared__ float vals[288];
    __shared__ int tok_s;
    if (g_is64) {
        const long long* xr = (const long long*)xraw + (size_t)m * 289;
        if (t == 0) tok_s = (int)xr[0];
        for (int i = t; i < 288; i += 192) vals[i] = (float)xr[1 + i];
    } else {
        const int* xr = (const int*)xraw + (size_t)m * 289;
        if (t == 0) tok_s = xr[0];
        for (int i = t; i < 288; i += 192) vals[i] = (float)xr[1 + i];
    }
    __syncthreads();
    int tok = tok_s;
    float c0 = emb[(size_t)tok * 192 + t];
    float c1 = reg_b[t];
    const float* rw = reg_w + (size_t)t * 64;
#pragma unroll 8
    for (int k = 0; k < 64; k++) c1 = fmaf(vals[k], rw[k], c1);
    float c2 = br_b[t];
    const float* bw = br_w + (size_t)t * 32;
#pragma unroll 8
    for (int k = 0; k < 32; k++) c2 = fmaf(vals[256 + k], bw[k], c2);
    float c3 = sh_b[t];
    const float* sw = sh_w + (size_t)t * 192;
#pragma unroll 8
    for (int k = 0; k < 192; k++) c3 = fmaf(vals[64 + k], sw[k], c3);
    float s0 = c0 / (1.f + expf(-c0));
    float s1 = c1 / (1.f + expf(-c1));
    float s2 = c2 / (1.f + expf(-c2));
    float s3 = c3 / (1.f + expf(-c3));
    size_t base = (size_t)m * 768;
    uint16_t h, l;
    split2h(s0, h, l); chi[base + t] = h;        clo[base + t] = l;
    split2h(s1, h, l); chi[base + 192 + t] = h;  clo[base + 192 + t] = l;
    split2h(s2, h, l); chi[base + 384 + t] = h;  clo[base + 384 + t] = l;
    split2h(s3, h, l); chi[base + 576 + t] = h;  clo[base + 576 + t] = l;
}

// ---------------- 3xFP16 GEMM (R11 mainloop) + optional pair-gate epilogue ----------------
#define TSTRIDE 40
#define PS (128 * TSTRIDE)
#define TG_DSMEM (2 * 4 * PS * 2)

__global__ __launch_bounds__(256, 2) void tgemm_k(
    const uint16_t* __restrict__ Ahg, const uint16_t* __restrict__ Alg, int lda,
    const uint16_t* __restrict__ Whg, const uint16_t* __restrict__ Wlg, int ldw,
    const float* __restrict__ bias, const float* __restrict__ resid,
    float* __restrict__ C, uint16_t* __restrict__ Chi, uint16_t* __restrict__ Clo,
    int ldc, int N, int K, int gatemode)
{
    extern __shared__ uint16_t dsm[];
    const uint32_t sb = smem_u32(dsm);

    const int tid = threadIdx.x;
    const int wid = tid >> 5, lane = tid & 31;
    const int wm = wid >> 2, wn = wid & 3;
    const int gid = lane >> 2, tig = lane & 3;

    const int bm = blockIdx.y * 128, bn = blockIdx.x * 128;

    const int lrow = tid >> 1, lsub = (tid & 1) * 16;
    const uint16_t* Agh = Ahg + (size_t)(bm + lrow) * lda;
    const uint16_t* Agl = Alg + (size_t)(bm + lrow) * lda;
    const int wrow = bn + lrow;
    const int wsafe = (wrow < N) ? wrow : 0;
    const uint16_t* Wgh = Whg + (size_t)wsafe * ldw;
    const uint16_t* Wgl = Wlg + (size_t)wsafe * ldw;

    const uint32_t dbase = sb + 2 * (uint32_t)(lrow * TSTRIDE + lsub);

    float acc[4][4][4];
#pragma unroll
    for (int i = 0; i < 4; i++)
#pragma unroll
        for (int j = 0; j < 4; j++)
#pragma unroll
            for (int e = 0; e < 4; e++) acc[i][j][e] = 0.f;

    const int NC = K >> 5;

#define ISSUE(c, buf)                                                        \
    do {                                                                     \
        const int ke = (c) * 32 + lsub;                                      \
        uint32_t d = dbase + (uint32_t)(buf) * (4 * PS * 2);                 \
        cpasync16(d, Agh + ke);               cpasync16(d + 16, Agh + ke + 8);\
        cpasync16(d + PS * 2, Agl + ke);      cpasync16(d + PS * 2 + 16, Agl + ke + 8);\
        cpasync16(d + 2 * PS * 2, Wgh + ke);  cpasync16(d + 2 * PS * 2 + 16, Wgh + ke + 8);\
        cpasync16(d + 3 * PS * 2, Wgl + ke);  cpasync16(d + 3 * PS * 2 + 16, Wgl + ke + 8);\
        asm volatile("cp.async.commit_group;" ::: "memory");                 \
    } while (0)

    ISSUE(0, 0);

    for (int c = 0; c < NC; c++) {
        const int buf = c & 1;
        if (c + 1 < NC) {
            ISSUE(c + 1, (c + 1) & 1);
            asm volatile("cp.async.wait_group 1;" ::: "memory");
        } else {
            asm volatile("cp.async.wait_group 0;" ::: "memory");
        }
        __syncthreads();

        const uint16_t* Ah = dsm + buf * 4 * PS;
        const uint16_t* Al = Ah + PS;
        const uint16_t* Bh = Ah + 2 * PS;
        const uint16_t* Bl = Ah + 3 * PS;
#pragma unroll
        for (int s = 0; s < 2; s++) {
            const int kk = s * 16 + 2 * tig;
            uint32_t bh[4][2], bl[4][2];
#pragma unroll
            for (int nt = 0; nt < 4; nt++) {
                const int n0 = (wn * 32 + nt * 8 + gid) * TSTRIDE + kk;
                bh[nt][0] = *(const uint32_t*)(Bh + n0);
                bh[nt][1] = *(const uint32_t*)(Bh + n0 + 8);
                bl[nt][0] = *(const uint32_t*)(Bl + n0);
                bl[nt][1] = *(const uint32_t*)(Bl + n0 + 8);
            }
#pragma unroll
            for (int mt = 0; mt < 4; mt++) {
                const int r0 = (wm * 64 + mt * 16 + gid) * TSTRIDE + kk;
                const int r1 = r0 + 8 * TSTRIDE;
                uint32_t ah[4], al[4];
                ah[0] = *(const uint32_t*)(Ah + r0); ah[1] = *(const uint32_t*)(Ah + r1);
                ah[2] = *(const uint32_t*)(Ah + r0 + 8); ah[3] = *(const uint32_t*)(Ah + r1 + 8);
                al[0] = *(const uint32_t*)(Al + r0); al[1] = *(const uint32_t*)(Al + r1);
                al[2] = *(const uint32_t*)(Al + r0 + 8); al[3] = *(const uint32_t*)(Al + r1 + 8);
#pragma unroll
                for (int nt = 0; nt < 4; nt++)
                    mma_f16(acc[mt][nt], ah, bh[nt][0], bh[nt][1]);
#pragma unroll
                for (int nt = 0; nt < 4; nt++)
                    mma_f16(acc[mt][nt], ah, bl[nt][0], bl[nt][1]);
#pragma unroll
                for (int nt = 0; nt < 4; nt++)
                    mma_f16(acc[mt][nt], al, bh[nt][0], bh[nt][1]);
            }
        }
        __syncthreads();
    }

    if (gatemode) {
        // pair-gate: even col = u (w1), odd col = v (w3); write silu(u)*v split at col gcol/2
#pragma unroll
        for (int mt = 0; mt < 4; mt++) {
            const int grow = bm + wm * 64 + mt * 16 + gid;
            const size_t r0o = (size_t)grow * ldc, r1o = (size_t)(grow + 8) * ldc;
#pragma unroll
            for (int nt = 0; nt < 4; nt++) {
                const int gcol = bn + wn * 32 + nt * 8 + tig * 2;
                if (gcol >= N) continue;
                const int j = gcol >> 1;
                const float b1v = bias[gcol], b3v = bias[gcol + 1];
                float u0 = acc[mt][nt][0] * WUNSCALE + b1v;
                float v0 = acc[mt][nt][1] * WUNSCALE + b3v;
                float r0 = u0 / (1.f + expf(-u0)) * v0;
                float u1 = acc[mt][nt][2] * WUNSCALE + b1v;
                float v1 = acc[mt][nt][3] * WUNSCALE + b3v;
                float r1 = u1 / (1.f + expf(-u1)) * v1;
                uint16_t h, l;
                split2h(r0, h, l); Chi[r0o + j] = h; Clo[r0o + j] = l;
                split2h(r1, h, l); Chi[r1o + j] = h; Clo[r1o + j] = l;
            }
        }
        return;
    }

#pragma unroll
    for (int mt = 0; mt < 4; mt++) {
        const int grow = bm + wm * 64 + mt * 16 + gid;
        const size_t r0o = (size_t)grow * ldc, r1o = (size_t)(grow + 8) * ldc;
#pragma unroll
        for (int nt = 0; nt < 4; nt++) {
            const int gcol = bn + wn * 32 + nt * 8 + tig * 2;
#pragma unroll
            for (int half = 0; half < 2; half++) {
                const int cc = gcol + half;
                if (cc >= N) continue;
                const size_t i0 = r0o + cc, i1 = r1o + cc;
                float v0 = acc[mt][nt][half] * WUNSCALE;
                float v1 = acc[mt][nt][2 + half] * WUNSCALE;
                if (bias) { const float b = bias[cc]; v0 += b; v1 += b; }
                if (resid) { v0 += resid[i0]; v1 += resid[i1]; }
                if (C) { C[i0] = v0; C[i1] = v1; }
                if (Chi) {
                    uint16_t h, l;
                    split2h(v0, h, l); Chi[i0] = h; Clo[i0] = l;
                    split2h(v1, h, l); Chi[i1] = h; Clo[i1] = l;
                }
            }
        }
    }
}

// ---------------- RMSNorm (split output) ----------------
__global__ __launch_bounds__(128) void rms_k(
    const float* __restrict__ h, const float* __restrict__ w,
    uint16_t* __restrict__ ohi, uint16_t* __restrict__ olo)
{
    int m = blockIdx.x, t = threadIdx.x;
    const float4* hr = (const float4*)(h + (size_t)m * 512);
    float4 v = hr[t];
    float ss = v.x * v.x + v.y * v.y + v.z * v.z + v.w * v.w;
#pragma unroll
    for (int off = 16; off; off >>= 1) ss += __shfl_down_sync(0xffffffffu, ss, off);
    __shared__ float red[4];
    __shared__ float sc_s;
    if ((t & 31) == 0) red[t >> 5] = ss;
    __syncthreads();
    if (t == 0) sc_s = rsqrtf((red[0] + red[1] + red[2] + red[3]) / 512.f + 1.1920929e-07f);
    __syncthreads();
    float sc = sc_s;
    float4 wv = ((const float4*)w)[t];
    float r0 = v.x * sc * wv.x, r1 = v.y * sc * wv.y, r2 = v.z * sc * wv.z, r3 = v.w * sc * wv.w;
    ushort4 hh, ll;
    split2h(r0, hh.x, ll.x); split2h(r1, hh.y, ll.y);
    split2h(r2, hh.z, ll.z); split2h(r3, hh.w, ll.w);
    ((ushort4*)(ohi + (size_t)m * 512))[t] = hh;
    ((ushort4*)(olo + (size_t)m * 512))[t] = ll;
}

// ---------------- LayerNorm + SiLU (in place, float) ----------------
__global__ __launch_bounds__(128) void lnsilu_k(
    float* __restrict__ h, const float* __restrict__ w, const float* __restrict__ b)
{
    int m = blockIdx.x, t = threadIdx.x;
    float4* hr = (float4*)(h + (size_t)m * 512);
    float4 v = hr[t];
    float s1 = v.x + v.y + v.z + v.w;
    float s2 = v.x * v.x + v.y * v.y + v.z * v.z + v.w * v.w;
#pragma unroll
    for (int off = 16; off; off >>= 1) {
        s1 += __shfl_down_sync(0xffffffffu, s1, off);
        s2 += __shfl_down_sync(0xffffffffu, s2, off);
    }
    __shared__ float red[8];
    __shared__ float st[2];
    if ((t & 31) == 0) { red[t >> 5] = s1; red[4 + (t >> 5)] = s2; }
    __syncthreads();
    if (t == 0) {
        float a = red[0] + red[1] + red[2] + red[3];
        float q = red[4] + red[5] + red[6] + red[7];
        float mean = a / 512.f;
        float var = q / 512.f - mean * mean;
        st[0] = mean; st[1] = rsqrtf(var + 1e-5f);
    }
    __syncthreads();
    float mean = st[0], rstd = st[1];
    float4 wv = ((const float4*)w)[t], bv = ((const float4*)b)[t];
    float x0 = (v.x - mean) * rstd * wv.x + bv.x;
    float x1 = (v.y - mean) * rstd * wv.y + bv.y;
    float x2 = (v.z - mean) * rstd * wv.z + bv.z;
    float x3 = (v.w - mean) * rstd * wv.w + bv.w;
    float4 r;
    r.x = x0 / (1.f + expf(-x0)); r.y = x1 / (1.f + expf(-x1));
    r.z = x2 / (1.f + expf(-x2)); r.w = x3 / (1.f + expf(-x3));
    hr[t] = r;
}

// ---------------- sliding-window attention: 512 thr, rope tables, linear split output ----------------
__global__ __launch_bounds__(512) void attn_k(const float* __restrict__ qkv,
                                              const float* __restrict__ rc,
                                              const float* __restrict__ rs,
                                              uint16_t* __restrict__ ohi,
                                              uint16_t* __restrict__ olo)
{
    extern __shared__ float sm[];
    float* Ks = sm;            // 256 x 64
    float* Vs = sm + 16384;    // 256 x 64
    const int n = blockIdx.x, hh = blockIdx.y, b = blockIdx.z;
    const int tid = threadIdx.x;

    {
        int d2 = tid & 31, j0 = tid >> 5;   // 16 warps
        for (int j = j0; j < 256; j += 16) {
            int p = (n - 1) * 128 + j;
            if (p >= 0) {
                size_t base = ((size_t)(b * LSEQ + p)) * 1536 + hh * 192 + d2 * 6;
                float k0 = qkv[base + 1], k1 = qkv[base + 4];
                float v0 = qkv[base + 2], v1 = qkv[base + 5];
                float cs = rc[p * 32 + d2], sn = rs[p * 32 + d2];
                Ks[j * 64 + 2 * d2]     = k0 * cs - k1 * sn;
                Ks[j * 64 + 2 * d2 + 1] = k0 * sn + k1 * cs;
                Vs[j * 64 + 2 * d2]     = v0;
                Vs[j * 64 + 2 * d2 + 1] = v1;
            } else {
                Ks[j * 64 + 2 * d2] = 0.f; Ks[j * 64 + 2 * d2 + 1] = 0.f;
                Vs[j * 64 + 2 * d2] = 0.f; Vs[j * 64 + 2 * d2 + 1] = 0.f;
            }
        }
    }
    const int qi = tid >> 2, quarter = tid & 3;   // 4 threads per query
    const int pq = n * 128 + qi;
    float q[16];
    {
        size_t base = ((size_t)(b * LSEQ + pq)) * 1536 + hh * 192;
#pragma unroll
        for (int t = 0; t < 8; t++) {
            int d2 = quarter * 8 + t;
            float q0 = qkv[base + d2 * 6], q1 = qkv[base + d2 * 6 + 3];
            float cs = rc[pq * 32 + d2], sn = rs[pq * 32 + d2];
            q[2 * t]     = q0 * cs - q1 * sn;
            q[2 * t + 1] = q0 * sn + q1 * cs;
        }
    }
    __syncthreads();

    const int jstart = (n == 0) ? 128 : qi;
    const int jend = qi + 128;

    float mx = -1e30f;
    for (int j = 0; j < 256; j++) {
        const float4* kr = (const float4*)(Ks + j * 64 + quarter * 16);
        float s = 0.f;
#pragma unroll
        for (int t = 0; t < 4; t++) {
            float4 kv = kr[t];
            s = fmaf(q[4 * t], kv.x, s); s = fmaf(q[4 * t + 1], kv.y, s);
            s = fmaf(q[4 * t + 2], kv.z, s); s = fmaf(q[4 * t + 3], kv.w, s);
        }
        s += __shfl_xor_sync(0xffffffffu, s, 1);
        s += __shfl_xor_sync(0xffffffffu, s, 2);
        if (j >= jstart && j <= jend) mx = fmaxf(mx, s);
    }
    float l = 0.f;
    float o[16];
#pragma unroll
    for (int t = 0; t < 16; t++) o[t] = 0.f;
    for (int j = 0; j < 256; j++) {
        const float4* kr = (const float4*)(Ks + j * 64 + quarter * 16);
        float s = 0.f;
#pragma unroll
        for (int t = 0; t < 4; t++) {
            float4 kv = kr[t];
            s = fmaf(q[4 * t], kv.x, s); s = fmaf(q[4 * t + 1], kv.y, s);
            s = fmaf(q[4 * t + 2], kv.z, s); s = fmaf(q[4 * t + 3], kv.w, s);
        }
        s += __shfl_xor_sync(0xffffffffu, s, 1);
        s += __shfl_xor_sync(0xffffffffu, s, 2);
        if (j >= jstart && j <= jend) {
            float p = __expf((s - mx) * 0.125f);
            l += p;
            const float4* vr = (const float4*)(Vs + j * 64 + quarter * 16);
#pragma unroll
            for (int t = 0; t < 4; t++) {
                float4 vv = vr[t];
                o[4 * t]     = fmaf(p, vv.x, o[4 * t]);
                o[4 * t + 1] = fmaf(p, vv.y, o[4 * t + 1]);
                o[4 * t + 2] = fmaf(p, vv.z, o[4 * t + 2]);
                o[4 * t + 3] = fmaf(p, vv.w, o[4 * t + 3]);
            }
        }
    }
    float invl = 1.f / l;
    // LINEAR split stores (matches tgemm's scalar-fragment layout)
    size_t obase = ((size_t)(b * LSEQ + pq)) * 512 + hh * 64 + quarter * 16;
#pragma unroll
    for (int u = 0; u < 4; u++) {
        ushort4 hh4, ll4;
        split2h(o[4 * u] * invl,     hh4.x, ll4.x);
        split2h(o[4 * u + 1] * invl, hh4.y, ll4.y);
        split2h(o[4 * u + 2] * invl, hh4.z, ll4.z);
        split2h(o[4 * u + 3] * invl, hh4.w, ll4.w);
        *(ushort4*)(ohi + obase + 4 * u) = hh4;
        *(ushort4*)(olo + obase + 4 * u) = ll4;
    }
}

// ---------------- head: LN+SiLU, 31-dim projection, postprocess ----------------
__device__ __forceinline__ float softplus_f(float x) { return x > 20.f ? x : log1pf(expf(x)); }

__global__ __launch_bounds__(256) void head_k(
    const float* __restrict__ h,
    const float* __restrict__ lw, const float* __restrict__ lb,
    const float* __restrict__ hw, const float* __restrict__ hb,
    float* __restrict__ out)
{
    int m = blockIdx.x, t = threadIdx.x;
    __shared__ float xs[512];
    __shared__ float red[16];
    __shared__ float ysh[31];
    __shared__ float st[2];
    const float* hr = h + (size_t)m * 512;
    float a = hr[t], b2 = hr[t + 256];
    float s1 = a + b2, s2 = a * a + b2 * b2;
#pragma unroll
    for (int off = 16; off; off >>= 1) {
        s1 += __shfl_down_sync(0xffffffffu, s1, off);
        s2 += __shfl_down_sync(0xffffffffu, s2, off);
    }
    if ((t & 31) == 0) { red[t >> 5] = s1; red[8 + (t >> 5)] = s2; }
    __syncthreads();
    if (t == 0) {
        float ss1 = 0.f, ss2 = 0.f;
        for (int i = 0; i < 8; i++) { ss1 += red[i]; ss2 += red[8 + i]; }
        float mean = ss1 / 512.f;
        float var = ss2 / 512.f - mean * mean;
        st[0] = mean; st[1] = rsqrtf(var + 1e-5f);
    }
    __syncthreads();
    float mean = st[0], rstd = st[1];
    float va = (a - mean) * rstd * lw[t] + lb[t];
    float vb = (b2 - mean) * rstd * lw[t + 256] + lb[t + 256];
    xs[t] = va / (1.f + expf(-va));
    xs[t + 256] = vb / (1.f + expf(-vb));
    __syncthreads();
    {
        int nn = t >> 3, p = t & 7;
        bool valid = nn < 31;
        const float* wr = hw + (size_t)(valid ? nn : 0) * 512;
        float acc = 0.f;
#pragma unroll 8
        for (int kk = 0; kk < 64; kk++) {
            int k = kk * 8 + p;
            acc = fmaf(xs[k], wr[k], acc);
        }
        acc += __shfl_down_sync(0xffffffffu, acc, 4, 8);
        acc += __shfl_down_sync(0xffffffffu, acc, 2, 8);
        acc += __shfl_down_sync(0xffffffffu, acc, 1, 8);
        if (valid && p == 0) ysh[nn] = acc + hb[nn];
    }
    __syncthreads();
    if (t == 0) {
        float y[31];
#pragma unroll
        for (int i = 0; i < 31; i++) y[i] = ysh[i];
        float* op = out + (size_t)m * 40;
        int am = 0;
        for (int i = 1; i < 11; i++) if (y[i] > y[am]) am = i;
        float fc_reg = softplus_f(y[11]);
        float fetch = (am < 10) ? (float)(am + 1) : fc_reg;
        int ae = 0;
        for (int i = 1; i < 11; i++) if (y[12 + i] > y[12 + ae]) ae = i;
        float ec_reg = softplus_f(y[23]);
        float execc = (ae < 10) ? (float)(ae + 1) : ec_reg;
        float bm_log = y[24];
        float bm = 1.f / (1.f + expf(-bm_log));
        float icm = fmaxf(y[25], fmaxf(y[26], y[27]));
        float e0 = expf(y[25] - icm), e1 = expf(y[26] - icm), e2 = expf(y[27] - icm);
        float is = e0 + e1 + e2;
        float dcm = fmaxf(y[28], fmaxf(y[29], y[30]));
        float d0 = expf(y[28] - dcm), d1 = expf(y[29] - dcm), d2 = expf(y[30] - dcm);
        float ds = d0 + d1 + d2;
        op[0] = fetch;
        for (int i = 0; i < 11; i++) op[1 + i] = y[i];
        op[12] = fc_reg;
        op[13] = execc;
        for (int i = 0; i < 11; i++) op[14 + i] = y[12 + i];
        op[25] = ec_reg;
        op[26] = bm;
        op[27] = e0 / is; op[28] = e1 / is; op[29] = e2 / is;
        op[30] = d0 / ds; op[31] = d1 / ds; op[32] = d2 / ds;
        op[33] = bm_log;
        op[34] = y[25]; op[35] = y[26]; op[36] = y[27];
        op[37] = y[28]; op[38] = y[29]; op[39] = y[30];
    }
}

// ---------------- launch ----------------
extern "C" void kernel_launch(void* const* d_in, const int* in_sizes, int n_in,
                              void* d_out, int out_size)
{
    const void*  x       = d_in[0];
    const float* emb     = (const float*)d_in[1];
    const float* reg_w   = (const float*)d_in[2];
    const float* reg_b   = (const float*)d_in[3];
    const float* br_w    = (const float*)d_in[4];
    const float* br_b    = (const float*)d_in[5];
    const float* sh_w    = (const float*)d_in[6];
    const float* sh_b    = (const float*)d_in[7];
    const float* inst_w  = (const float*)d_in[8];
    const float* inst_b  = (const float*)d_in[9];
    const float* enc_ln_w = (const float*)d_in[10];
    const float* enc_ln_b = (const float*)d_in[11];
    const float* qkv_w   = (const float*)d_in[12];
    const float* out_w   = (const float*)d_in[13];
    const float* out_b   = (const float*)d_in[14];
    const float* w1_w    = (const float*)d_in[15];
    const float* w1_b    = (const float*)d_in[16];
    const float* w3_w    = (const float*)d_in[17];
    const float* w3_b    = (const float*)d_in[18];
    const float* w2_w    = (const float*)d_in[19];
    const float* w2_b    = (const float*)d_in[20];
    const float* n1_w    = (const float*)d_in[21];
    const float* n2_w    = (const float*)d_in[22];
    const float* head_ln_w = (const float*)d_in[23];
    const float* head_ln_b = (const float*)d_in[24];
    const float* head_w  = (const float*)d_in[25];
    const float* head_b  = (const float*)d_in[26];
    float* out = (float*)d_out;

    void *p;
    cudaGetSymbolAddress(&p, g_cat_hi);  uint16_t* cat_hi = (uint16_t*)p;
    cudaGetSymbolAddress(&p, g_cat_lo);  uint16_t* cat_lo = (uint16_t*)p;
    cudaGetSymbolAddress(&p, g_h);       float* h = (float*)p;
    cudaGetSymbolAddress(&p, g_xn_hi);   uint16_t* xn_hi = (uint16_t*)p;
    cudaGetSymbolAddress(&p, g_xn_lo);   uint16_t* xn_lo = (uint16_t*)p;
    cudaGetSymbolAddress(&p, g_qkv);     float* qkv = (float*)p;
    cudaGetSymbolAddress(&p, g_att_hi);  uint16_t* att_hi = (uint16_t*)p;
    cudaGetSymbolAddress(&p, g_att_lo);  uint16_t* att_lo = (uint16_t*)p;
    cudaGetSymbolAddress(&p, g_u_hi);    uint16_t* u_hi = (uint16_t*)p;
    cudaGetSymbolAddress(&p, g_u_lo);    uint16_t* u_lo = (uint16_t*)p;
    cudaGetSymbolAddress(&p, g_w2p);     float* w2p = (float*)p;
    cudaGetSymbolAddress(&p, g_whi);     uint16_t* whi = (uint16_t*)p;
    cudaGetSymbolAddress(&p, g_wlo);     uint16_t* wlo = (uint16_t*)p;
    cudaGetSymbolAddress(&p, g_bg);      float* bg = (float*)p;
    cudaGetSymbolAddress(&p, g_ropec);   float* ropec = (float*)p;
    cudaGetSymbolAddress(&p, g_ropes);   float* ropes = (float*)p;

    cudaFuncSetAttribute(attn_k, cudaFuncAttributeMaxDynamicSharedMemorySize, 131072);
    cudaFuncSetAttribute(tgemm_k, cudaFuncAttributeMaxDynamicSharedMemorySize, TG_DSMEM);

    detect_k<<<1, 1>>>((const int*)x);
    embed_k<<<NTOK, 192>>>(x, emb, reg_w, reg_b, br_w, br_b, sh_w, sh_b, cat_hi, cat_lo);
    padw2_k<<<1536, 256>>>(w2_w, w2p);
    ropetab_k<<<LSEQ, 32>>>(ropec, ropes);

    splitw_k<<<1024, 256>>>(inst_w, whi + OFF_INST, wlo + OFF_INST, CNT_INST);
    splitw_k<<<2048, 256>>>(qkv_w,  whi + OFF_QKV,  wlo + OFF_QKV,  CNT_QKV);
    splitw_k<<<1024, 256>>>(out_w,  whi + OFF_OUT,  wlo + OFF_OUT,  CNT_OUT);
    splitwg_k<<<2048, 256>>>(w1_w, w3_w, whi + OFF_WG, wlo + OFF_WG);
    splitw_k<<<2048, 256>>>(w2p,    whi + OFF_W2,   wlo + OFF_W2,   CNT_W2);
    bgbuild_k<<<(3 * NWG + 255) / 256, 256>>>(w1_b, w3_b, bg);

    // encoder: h = silu(cat) @ inst_w.T + inst_b
    tgemm_k<<<dim3(4, 64), 256, TG_DSMEM>>>(cat_hi, cat_lo, 768,
                                            whi + OFF_INST, wlo + OFF_INST, 768,
                                            inst_b, nullptr,
                                            h, nullptr, nullptr, 512, 512, 768, 0);
    lnsilu_k<<<NTOK, 128>>>(h, enc_ln_w, enc_ln_b);

    for (int l = 0; l < 3; l++) {
        rms_k<<<NTOK, 128>>>(h, n1_w + l * 512, xn_hi, xn_lo);
        tgemm_k<<<dim3(12, 64), 256, TG_DSMEM>>>(xn_hi, xn_lo, 512,
                                                 whi + OFF_QKV + (size_t)l * 1536 * 512,
                                                 wlo + OFF_QKV + (size_t)l * 1536 * 512, 512,
                                                 nullptr, nullptr,
                                                 qkv, nullptr, nullptr, 1536, 1536, 512, 0);
        attn_k<<<dim3(16, 8, 4), 512, 131072>>>(qkv, ropec, ropes, att_hi, att_lo);
        tgemm_k<<<dim3(4, 64), 256, TG_DSMEM>>>(att_hi, att_lo, 512,
                                                whi + OFF_OUT + (size_t)l * 512 * 512,
                                                wlo + OFF_OUT + (size_t)l * 512 * 512, 512,
                                                out_b + l * 512, h,
                                                h, nullptr, nullptr, 512, 512, 512, 0);
        rms_k<<<NTOK, 128>>>(h, n2_w + l * 512, xn_hi, xn_lo);
        tgemm_k<<<dim3(22, 64), 256, TG_DSMEM>>>(xn_hi, xn_lo, 512,
                                                 whi + OFF_WG + (size_t)l * NWG * 512,
                                                 wlo + OFF_WG + (size_t)l * NWG * 512, 512,
                                                 bg + l * NWG, nullptr,
                                                 nullptr, u_hi, u_lo, DFFP, NWG, 512, 1);
        tgemm_k<<<dim3(4, 64), 256, TG_DSMEM>>>(u_hi, u_lo, DFFP,
                                                whi + OFF_W2 + (size_t)l * 512 * DFFP,
                                                wlo + OFF_W2 + (size_t)l * 512 * DFFP, DFFP,
                                                w2_b + l * 512, h,
                                                h, nullptr, nullptr, 512, 512, 1376, 0);
    }

    head_k<<<NTOK, 256>>>(h, head_ln_w, head_ln_b, head_w, head_b, out);
}

// round 14
// speedup vs baseline: 1.1598x; 1.1598x over previous
#include <cuda_runtime.h>
#include <cuda_fp16.h>
#include <cstdint>
#include <cstddef>

#define NTOK 8192
#define LSEQ 2048
#define DMODEL 512
#define DFF 1365
#define DFFP 1376

// weight-plane offsets (fp16 elements)
#define OFF_INST 0
#define CNT_INST (512 * 768)
#define OFF_QKV  (OFF_INST + CNT_INST)
#define CNT_QKV  (3 * 1536 * 512)
#define OFF_OUT  (OFF_QKV + CNT_QKV)
#define CNT_OUT  (3 * 512 * 512)
#define OFF_W1   (OFF_OUT + CNT_OUT)
#define CNT_W1   (3 * DFF * 512)
#define OFF_W3   (OFF_W1 + CNT_W1)
#define CNT_W3   (3 * DFF * 512)
#define OFF_W2   (OFF_W3 + CNT_W3)
#define CNT_W2   (3 * 512 * DFFP)
#define WTOT     (OFF_W2 + CNT_W2)

#define WSCALE   64.0f
#define WUNSCALE 0.015625f

// ---------------- scratch (device globals; allocation-free) ----------------
__device__ __align__(16) uint16_t g_cat_hi[NTOK * 768];
__device__ __align__(16) uint16_t g_cat_lo[NTOK * 768];
__device__ __align__(16) float    g_h[NTOK * 512];
__device__ __align__(16) uint16_t g_xn_hi[NTOK * 512];
__device__ __align__(16) uint16_t g_xn_lo[NTOK * 512];
__device__ __align__(16) float    g_qkv[NTOK * 1536];
__device__ __align__(16) uint16_t g_att_hi[NTOK * 512];
__device__ __align__(16) uint16_t g_att_lo[NTOK * 512];
__device__ __align__(16) float    g_uf[NTOK * DFFP];      // w1 output (pads never read)
__device__ __align__(16) uint16_t g_u_hi[NTOK * DFFP];    // pads stay 0 (static zero init)
__device__ __align__(16) uint16_t g_u_lo[NTOK * DFFP];
__device__ __align__(16) float    g_w2p[3 * 512 * DFFP];
__device__ __align__(16) uint16_t g_whi[WTOT];
__device__ __align__(16) uint16_t g_wlo[WTOT];
__device__ __align__(16) float    g_ropec[LSEQ * 32];
__device__ __align__(16) float    g_ropes[LSEQ * 32];
__device__ int g_is64;

// ---------------- helpers ----------------
__device__ __forceinline__ uint32_t smem_u32(const void* p) {
    uint32_t a;
    asm("{ .reg .u64 t; cvta.to.shared.u64 t, %1; cvt.u32.u64 %0, t; }" : "=r"(a) : "l"(p));
    return a;
}
__device__ __forceinline__ void split2h(float x, uint16_t& h, uint16_t& l) {
    __half hh = __float2half_rn(x);
    __half ll = __float2half_rn(x - __half2float(hh));
    h = __half_as_ushort(hh);
    l = __half_as_ushort(ll);
}
__device__ __forceinline__ void mma_f16(float* d, const uint32_t* a, uint32_t b0, uint32_t b1) {
    asm volatile(
        "mma.sync.aligned.m16n8k16.row.col.f32.f16.f16.f32 "
        "{%0,%1,%2,%3}, {%4,%5,%6,%7}, {%8,%9}, {%0,%1,%2,%3};"
        : "+f"(d[0]), "+f"(d[1]), "+f"(d[2]), "+f"(d[3])
        : "r"(a[0]), "r"(a[1]), "r"(a[2]), "r"(a[3]), "r"(b0), "r"(b1));
}
__device__ __forceinline__ void cpasync16(uint32_t dst, const void* src) {
    asm volatile("cp.async.cg.shared.global [%0], [%1], 16;" :: "r"(dst), "l"(src) : "memory");
}

// ---------------- dtype probe for x (int64 vs int32) ----------------
__global__ void detect_k(const int* x) {
    long long s = 0;
    for (int i = 1; i < 8192; i += 2) { int v = x[i]; s += (v < 0) ? -(long long)v : (long long)v; }
    g_is64 = (s == 0) ? 1 : 0;
}

// ---------------- rope tables (bitwise-identical to in-kernel sincosf) ----------------
__global__ void ropetab_k(float* rc, float* rs) {
    int p = blockIdx.x, d2 = threadIdx.x;
    float inv = expf((float)d2 * -0.28782313662425572f);
    float sn, cs;
    sincosf((float)p * inv, &sn, &cs);
    rc[p * 32 + d2] = cs;
    rs[p * 32 + d2] = sn;
}

// ---------------- split weights (scaled by 64) into fp16 hi/lo planes ----------------
__global__ void splitw_k(const float* __restrict__ src, uint16_t* __restrict__ hi,
                         uint16_t* __restrict__ lo, int n)
{
    int stride = gridDim.x * 256;
    for (int i = blockIdx.x * 256 + threadIdx.x; i < n; i += stride) {
        uint16_t h, l;
        split2h(src[i] * WSCALE, h, l);
        hi[i] = h; lo[i] = l;
    }
}

// ---------------- pad w2 (3,512,1365) -> (3,512,1376) ----------------
__global__ void padw2_k(const float* __restrict__ w2, float* __restrict__ o)
{
    int row = blockIdx.x;  // 0..1535
    const float* src = w2 + (size_t)row * DFF;
    float* dst = o + (size_t)row * DFFP;
    for (int k = threadIdx.x; k < DFFP; k += 256) dst[k] = (k < DFF) ? src[k] : 0.f;
}

// ---------------- embed + input projections + silu (split output) ----------------
__global__ __launch_bounds__(192) void embed_k(
    const void* __restrict__ xraw,
    const float* __restrict__ emb,
    const float* __restrict__ reg_w, const float* __restrict__ reg_b,
    const float* __restrict__ br_w,  const float* __restrict__ br_b,
    const float* __restrict__ sh_w,  const float* __restrict__ sh_b,
    uint16_t* __restrict__ chi, uint16_t* __restrict__ clo)
{
    int m = blockIdx.x;
    int t = threadIdx.x;
    __shared__ float vals[288];
    __shared__ int tok_s;
    if (g_is64) {
        const long long* xr = (const long long*)xraw + (size_t)m * 289;
        if (t == 0) tok_s = (int)xr[0];
        for (int i = t; i < 288; i += 192) vals[i] = (float)xr[1 + i];
    } else {
        const int* xr = (const int*)xraw + (size_t)m * 289;
        if (t == 0) tok_s = xr[0];
        for (int i = t; i < 288; i += 192) vals[i] = (float)xr[1 + i];
    }
    __syncthreads();
    int tok = tok_s;
    float c0 = emb[(size_t)tok * 192 + t];
    float c1 = reg_b[t];
    const float* rw = reg_w + (size_t)t * 64;
#pragma unroll 8
    for (int k = 0; k < 64; k++) c1 = fmaf(vals[k], rw[k], c1);
    float c2 = br_b[t];
    const float* bw = br_w + (size_t)t * 32;
#pragma unroll 8
    for (int k = 0; k < 32; k++) c2 = fmaf(vals[256 + k], bw[k], c2);
    float c3 = sh_b[t];
    const float* sw = sh_w + (size_t)t * 192;
#pragma unroll 8
    for (int k = 0; k < 192; k++) c3 = fmaf(vals[64 + k], sw[k], c3);
    float s0 = c0 / (1.f + expf(-c0));
    float s1 = c1 / (1.f + expf(-c1));
    float s2 = c2 / (1.f + expf(-c2));
    float s3 = c3 / (1.f + expf(-c3));
    size_t base = (size_t)m * 768;
    uint16_t h, l;
    split2h(s0, h, l); chi[base + t] = h;        clo[base + t] = l;
    split2h(s1, h, l); chi[base + 192 + t] = h;  clo[base + 192 + t] = l;
    split2h(s2, h, l); chi[base + 384 + t] = h;  clo[base + 384 + t] = l;
    split2h(s3, h, l); chi[base + 576 + t] = h;  clo[base + 576 + t] = l;
}

// ---------------- 3xFP16 GEMM: pre-split fp16 hi/lo planes, cp.async, scalar frags ----------------
// C = (A @ (64 W)^T)/64; optional bias, gate (C *= silu(gate)), resid; float and/or split out.
// CTA 128x128, BK=32 (2 x k16 steps), 256 threads (8 warps 2x4), warp tile 64x32.
// smem: fp16, row stride 40 elems (80B) -> conflict-free frag loads, 16B-aligned cp.async.
// Inner MMA order interleaved across nt (dependency distance 4) — per-acc order hh,hl,lh unchanged.
#define TSTRIDE 40
#define PS (128 * TSTRIDE)
#define TG_DSMEM (2 * 4 * PS * 2)

__global__ __launch_bounds__(256, 2) void tgemm_k(
    const uint16_t* __restrict__ Ahg, const uint16_t* __restrict__ Alg, int lda,
    const uint16_t* __restrict__ Whg, const uint16_t* __restrict__ Wlg, int ldw,
    const float* __restrict__ bias, const float* __restrict__ resid,
    const float* __restrict__ gate,
    float* __restrict__ C, uint16_t* __restrict__ Chi, uint16_t* __restrict__ Clo,
    int ldc, int N, int K)
{
    extern __shared__ uint16_t dsm[];
    const uint32_t sb = smem_u32(dsm);

    const int tid = threadIdx.x;
    const int wid = tid >> 5, lane = tid & 31;
    const int wm = wid >> 2, wn = wid & 3;
    const int gid = lane >> 2, tig = lane & 3;

    const int bm = blockIdx.y * 128, bn = blockIdx.x * 128;

    const int lrow = tid >> 1, lsub = (tid & 1) * 16;
    const uint16_t* Agh = Ahg + (size_t)(bm + lrow) * lda;
    const uint16_t* Agl = Alg + (size_t)(bm + lrow) * lda;
    const int wrow = bn + lrow;
    const int wsafe = (wrow < N) ? wrow : 0;
    const uint16_t* Wgh = Whg + (size_t)wsafe * ldw;
    const uint16_t* Wgl = Wlg + (size_t)wsafe * ldw;

    const uint32_t dbase = sb + 2 * (uint32_t)(lrow * TSTRIDE + lsub);

    float acc[4][4][4];
#pragma unroll
    for (int i = 0; i < 4; i++)
#pragma unroll
        for (int j = 0; j < 4; j++)
#pragma unroll
            for (int e = 0; e < 4; e++) acc[i][j][e] = 0.f;

    const int NC = K >> 5;

#define ISSUE(c, buf)                                                        \
    do {                                                                     \
        const int ke = (c) * 32 + lsub;                                      \
        uint32_t d = dbase + (uint32_t)(buf) * (4 * PS * 2);                 \
        cpasync16(d, Agh + ke);               cpasync16(d + 16, Agh + ke + 8);\
        cpasync16(d + PS * 2, Agl + ke);      cpasync16(d + PS * 2 + 16, Agl + ke + 8);\
        cpasync16(d + 2 * PS * 2, Wgh + ke);  cpasync16(d + 2 * PS * 2 + 16, Wgh + ke + 8);\
        cpasync16(d + 3 * PS * 2, Wgl + ke);  cpasync16(d + 3 * PS * 2 + 16, Wgl + ke + 8);\
        asm volatile("cp.async.commit_group;" ::: "memory");                 \
    } while (0)

    ISSUE(0, 0);

    for (int c = 0; c < NC; c++) {
        const int buf = c & 1;
        if (c + 1 < NC) {
            ISSUE(c + 1, (c + 1) & 1);
            asm volatile("cp.async.wait_group 1;" ::: "memory");
        } else {
            asm volatile("cp.async.wait_group 0;" ::: "memory");
        }
        __syncthreads();

        const uint16_t* Ah = dsm + buf * 4 * PS;
        const uint16_t* Al = Ah + PS;
        const uint16_t* Bh = Ah + 2 * PS;
        const uint16_t* Bl = Ah + 3 * PS;
#pragma unroll
        for (int s = 0; s < 2; s++) {
            const int kk = s * 16 + 2 * tig;
            uint32_t bh[4][2], bl[4][2];
#pragma unroll
            for (int nt = 0; nt < 4; nt++) {
                const int n0 = (wn * 32 + nt * 8 + gid) * TSTRIDE + kk;
                bh[nt][0] = *(const uint32_t*)(Bh + n0);
                bh[nt][1] = *(const uint32_t*)(Bh + n0 + 8);
                bl[nt][0] = *(const uint32_t*)(Bl + n0);
                bl[nt][1] = *(const uint32_t*)(Bl + n0 + 8);
            }
#pragma unroll
            for (int mt = 0; mt < 4; mt++) {
                const int r0 = (wm * 64 + mt * 16 + gid) * TSTRIDE + kk;
                const int r1 = r0 + 8 * TSTRIDE;
                uint32_t ah[4], al[4];
                ah[0] = *(const uint32_t*)(Ah + r0); ah[1] = *(const uint32_t*)(Ah + r1);
                ah[2] = *(const uint32_t*)(Ah + r0 + 8); ah[3] = *(const uint32_t*)(Ah + r1 + 8);
                al[0] = *(const uint32_t*)(Al + r0); al[1] = *(const uint32_t*)(Al + r1);
                al[2] = *(const uint32_t*)(Al + r0 + 8); al[3] = *(const uint32_t*)(Al + r1 + 8);
#pragma unroll
                for (int nt = 0; nt < 4; nt++)
                    mma_f16(acc[mt][nt], ah, bh[nt][0], bh[nt][1]);
#pragma unroll
                for (int nt = 0; nt < 4; nt++)
                    mma_f16(acc[mt][nt], ah, bl[nt][0], bl[nt][1]);
#pragma unroll
                for (int nt = 0; nt < 4; nt++)
                    mma_f16(acc[mt][nt], al, bh[nt][0], bh[nt][1]);
            }
        }
        __syncthreads();
    }

    // epilogue (unscale weights by 1/64 first)
#pragma unroll
    for (int mt = 0; mt < 4; mt++) {
        const int grow = bm + wm * 64 + mt * 16 + gid;
        const size_t r0o = (size_t)grow * ldc, r1o = (size_t)(grow + 8) * ldc;
#pragma unroll
        for (int nt = 0; nt < 4; nt++) {
            const int gcol = bn + wn * 32 + nt * 8 + tig * 2;
#pragma unroll
            for (int half = 0; half < 2; half++) {
                const int cc = gcol + half;
                if (cc >= N) continue;
                const size_t i0 = r0o + cc, i1 = r1o + cc;
                float v0 = acc[mt][nt][half] * WUNSCALE;
                float v1 = acc[mt][nt][2 + half] * WUNSCALE;
                if (bias) { const float b = bias[cc]; v0 += b; v1 += b; }
                if (gate) {
                    const float gv0 = gate[i0], gv1 = gate[i1];
                    v0 *= gv0 / (1.f + expf(-gv0));
                    v1 *= gv1 / (1.f + expf(-gv1));
                }
                if (resid) { v0 += resid[i0]; v1 += resid[i1]; }
                if (C) { C[i0] = v0; C[i1] = v1; }
                if (Chi) {
                    uint16_t h, l;
                    split2h(v0, h, l); Chi[i0] = h; Clo[i0] = l;
                    split2h(v1, h, l); Chi[i1] = h; Clo[i1] = l;
                }
            }
        }
    }
}

// ---------------- RMSNorm (split output) ----------------
__global__ __launch_bounds__(128) void rms_k(
    const float* __restrict__ h, const float* __restrict__ w,
    uint16_t* __restrict__ ohi, uint16_t* __restrict__ olo)
{
    int m = blockIdx.x, t = threadIdx.x;
    const float4* hr = (const float4*)(h + (size_t)m * 512);
    float4 v = hr[t];
    float ss = v.x * v.x + v.y * v.y + v.z * v.z + v.w * v.w;
#pragma unroll
    for (int off = 16; off; off >>= 1) ss += __shfl_down_sync(0xffffffffu, ss, off);
    __shared__ float red[4];
    __shared__ float sc_s;
    if ((t & 31) == 0) red[t >> 5] = ss;
    __syncthreads();
    if (t == 0) sc_s = rsqrtf((red[0] + red[1] + red[2] + red[3]) / 512.f + 1.1920929e-07f);
    __syncthreads();
    float sc = sc_s;
    float4 wv = ((const float4*)w)[t];
    float r0 = v.x * sc * wv.x, r1 = v.y * sc * wv.y, r2 = v.z * sc * wv.z, r3 = v.w * sc * wv.w;
    ushort4 hh, ll;
    split2h(r0, hh.x, ll.x); split2h(r1, hh.y, ll.y);
    split2h(r2, hh.z, ll.z); split2h(r3, hh.w, ll.w);
    ((ushort4*)(ohi + (size_t)m * 512))[t] = hh;
    ((ushort4*)(olo + (size_t)m * 512))[t] = ll;
}

// ---------------- LayerNorm + SiLU (in place, float) ----------------
__global__ __launch_bounds__(128) void lnsilu_k(
    float* __restrict__ h, const float* __restrict__ w, const float* __restrict__ b)
{
    int m = blockIdx.x, t = threadIdx.x;
    float4* hr = (float4*)(h + (size_t)m * 512);
    float4 v = hr[t];
    float s1 = v.x + v.y + v.z + v.w;
    float s2 = v.x * v.x + v.y * v.y + v.z * v.z + v.w * v.w;
#pragma unroll
    for (int off = 16; off; off >>= 1) {
        s1 += __shfl_down_sync(0xffffffffu, s1, off);
        s2 += __shfl_down_sync(0xffffffffu, s2, off);
    }
    __shared__ float red[8];
    __shared__ float st[2];
    if ((t & 31) == 0) { red[t >> 5] = s1; red[4 + (t >> 5)] = s2; }
    __syncthreads();
    if (t == 0) {
        float a = red[0] + red[1] + red[2] + red[3];
        float q = red[4] + red[5] + red[6] + red[7];
        float mean = a / 512.f;
        float var = q / 512.f - mean * mean;
        st[0] = mean; st[1] = rsqrtf(var + 1e-5f);
    }
    __syncthreads();
    float mean = st[0], rstd = st[1];
    float4 wv = ((const float4*)w)[t], bv = ((const float4*)b)[t];
    float x0 = (v.x - mean) * rstd * wv.x + bv.x;
    float x1 = (v.y - mean) * rstd * wv.y + bv.y;
    float x2 = (v.z - mean) * rstd * wv.z + bv.z;
    float x3 = (v.w - mean) * rstd * wv.w + bv.w;
    float4 r;
    r.x = x0 / (1.f + expf(-x0)); r.y = x1 / (1.f + expf(-x1));
    r.z = x2 / (1.f + expf(-x2)); r.w = x3 / (1.f + expf(-x3));
    hr[t] = r;
}

// ---------------- sliding-window attention (R11 structure + rope tables) ----------------
__global__ __launch_bounds__(256) void attn_k(const float* __restrict__ qkv,
                                              const float* __restrict__ rc,
                                              const float* __restrict__ rs,
                                              uint16_t* __restrict__ ohi,
                                              uint16_t* __restrict__ olo)
{
    extern __shared__ float sm[];
    float* Ks = sm;            // 256 x 64
    float* Vs = sm + 16384;    // 256 x 64
    const int n = blockIdx.x, hh = blockIdx.y, b = blockIdx.z;
    const int tid = threadIdx.x;

    {
        int d2 = tid & 31, j0 = tid >> 5;
        for (int j = j0; j < 256; j += 8) {
            int p = (n - 1) * 128 + j;
            if (p >= 0) {
                size_t base = ((size_t)(b * LSEQ + p)) * 1536 + hh * 192 + d2 * 6;
                float k0 = qkv[base + 1], k1 = qkv[base + 4];
                float v0 = qkv[base + 2], v1 = qkv[base + 5];
                float cs = rc[p * 32 + d2], sn = rs[p * 32 + d2];
                Ks[j * 64 + 2 * d2]     = k0 * cs - k1 * sn;
                Ks[j * 64 + 2 * d2 + 1] = k0 * sn + k1 * cs;
                Vs[j * 64 + 2 * d2]     = v0;
                Vs[j * 64 + 2 * d2 + 1] = v1;
            } else {
                Ks[j * 64 + 2 * d2] = 0.f; Ks[j * 64 + 2 * d2 + 1] = 0.f;
                Vs[j * 64 + 2 * d2] = 0.f; Vs[j * 64 + 2 * d2 + 1] = 0.f;
            }
        }
    }
    const int qi = tid >> 1, half = tid & 1;
    const int pq = n * 128 + qi;
    float q[32];
    {
        size_t base = ((size_t)(b * LSEQ + pq)) * 1536 + hh * 192;
#pragma unroll
        for (int t = 0; t < 16; t++) {
            int d2 = half * 16 + t;
            float q0 = qkv[base + d2 * 6], q1 = qkv[base + d2 * 6 + 3];
            float cs = rc[pq * 32 + d2], sn = rs[pq * 32 + d2];
            q[2 * t]     = q0 * cs - q1 * sn;
            q[2 * t + 1] = q0 * sn + q1 * cs;
        }
    }
    __syncthreads();

    const int jstart = (n == 0) ? 128 : qi;
    const int jend = qi + 128;

    float mx = -1e30f;
    for (int j = 0; j < 256; j++) {
        const float4* kr = (const float4*)(Ks + j * 64 + half * 32);
        float s = 0.f;
#pragma unroll
        for (int t = 0; t < 8; t++) {
            float4 kv = kr[t];
            s = fmaf(q[4 * t], kv.x, s); s = fmaf(q[4 * t + 1], kv.y, s);
            s = fmaf(q[4 * t + 2], kv.z, s); s = fmaf(q[4 * t + 3], kv.w, s);
        }
        s += __shfl_xor_sync(0xffffffffu, s, 1);
        if (j >= jstart && j <= jend) mx = fmaxf(mx, s);
    }
    float l = 0.f;
    float o[32];
#pragma unroll
    for (int t = 0; t < 32; t++) o[t] = 0.f;
    for (int j = 0; j < 256; j++) {
        const float4* kr = (const float4*)(Ks + j * 64 + half * 32);
        float s = 0.f;
#pragma unroll
        for (int t = 0; t < 8; t++) {
            float4 kv = kr[t];
            s = fmaf(q[4 * t], kv.x, s); s = fmaf(q[4 * t + 1], kv.y, s);
            s = fmaf(q[4 * t + 2], kv.z, s); s = fmaf(q[4 * t + 3], kv.w, s);
        }
        s += __shfl_xor_sync(0xffffffffu, s, 1);
        if (j >= jstart && j <= jend) {
            float p = __expf((s - mx) * 0.125f);
            l += p;
            const float4* vr = (const float4*)(Vs + j * 64 + half * 32);
#pragma unroll
            for (int t = 0; t < 8; t++) {
                float4 vv = vr[t];
                o[4 * t]     = fmaf(p, vv.x, o[4 * t]);
                o[4 * t + 1] = fmaf(p, vv.y, o[4 * t + 1]);
                o[4 * t + 2] = fmaf(p, vv.z, o[4 * t + 2]);
                o[4 * t + 3] = fmaf(p, vv.w, o[4 * t + 3]);
            }
        }
    }
    float invl = 1.f / l;
    size_t obase = ((size_t)(b * LSEQ + pq)) * 512 + hh * 64 + half * 32;
#pragma unroll
    for (int t = 0; t < 8; t++) {
        ushort4 hh4, ll4;
        split2h(o[4 * t] * invl,     hh4.x, ll4.x);
        split2h(o[4 * t + 1] * invl, hh4.y, ll4.y);
        split2h(o[4 * t + 2] * invl, hh4.z, ll4.z);
        split2h(o[4 * t + 3] * invl, hh4.w, ll4.w);
        ((ushort4*)(ohi + obase))[t] = hh4;
        ((ushort4*)(olo + obase))[t] = ll4;
    }
}

// ---------------- head: LN+SiLU, 31-dim projection, postprocess ----------------
__device__ __forceinline__ float softplus_f(float x) { return x > 20.f ? x : log1pf(expf(x)); }

__global__ __launch_bounds__(256) void head_k(
    const float* __restrict__ h,
    const float* __restrict__ lw, const float* __restrict__ lb,
    const float* __restrict__ hw, const float* __restrict__ hb,
    float* __restrict__ out)
{
    int m = blockIdx.x, t = threadIdx.x;
    __shared__ float xs[512];
    __shared__ float red[16];
    __shared__ float ysh[31];
    __shared__ float st[2];
    const float* hr = h + (size_t)m * 512;
    float a = hr[t], b2 = hr[t + 256];
    float s1 = a + b2, s2 = a * a + b2 * b2;
#pragma unroll
    for (int off = 16; off; off >>= 1) {
        s1 += __shfl_down_sync(0xffffffffu, s1, off);
        s2 += __shfl_down_sync(0xffffffffu, s2, off);
    }
    if ((t & 31) == 0) { red[t >> 5] = s1; red[8 + (t >> 5)] = s2; }
    __syncthreads();
    if (t == 0) {
        float ss1 = 0.f, ss2 = 0.f;
        for (int i = 0; i < 8; i++) { ss1 += red[i]; ss2 += red[8 + i]; }
        float mean = ss1 / 512.f;
        float var = ss2 / 512.f - mean * mean;
        st[0] = mean; st[1] = rsqrtf(var + 1e-5f);
    }
    __syncthreads();
    float mean = st[0], rstd = st[1];
    float va = (a - mean) * rstd * lw[t] + lb[t];
    float vb = (b2 - mean) * rstd * lw[t + 256] + lb[t + 256];
    xs[t] = va / (1.f + expf(-va));
    xs[t + 256] = vb / (1.f + expf(-vb));
    __syncthreads();
    {
        int nn = t >> 3, p = t & 7;
        bool valid = nn < 31;
        const float* wr = hw + (size_t)(valid ? nn : 0) * 512;
        float acc = 0.f;
#pragma unroll 8
        for (int kk = 0; kk < 64; kk++) {
            int k = kk * 8 + p;
            acc = fmaf(xs[k], wr[k], acc);
        }
        acc += __shfl_down_sync(0xffffffffu, acc, 4, 8);
        acc += __shfl_down_sync(0xffffffffu, acc, 2, 8);
        acc += __shfl_down_sync(0xffffffffu, acc, 1, 8);
        if (valid && p == 0) ysh[nn] = acc + hb[nn];
    }
    __syncthreads();
    if (t == 0) {
        float y[31];
#pragma unroll
        for (int i = 0; i < 31; i++) y[i] = ysh[i];
        float* op = out + (size_t)m * 40;
        int am = 0;
        for (int i = 1; i < 11; i++) if (y[i] > y[am]) am = i;
        float fc_reg = softplus_f(y[11]);
        float fetch = (am < 10) ? (float)(am + 1) : fc_reg;
        int ae = 0;
        for (int i = 1; i < 11; i++) if (y[12 + i] > y[12 + ae]) ae = i;
        float ec_reg = softplus_f(y[23]);
        float execc = (ae < 10) ? (float)(ae + 1) : ec_reg;
        float bm_log = y[24];
        float bm = 1.f / (1.f + expf(-bm_log));
        float icm = fmaxf(y[25], fmaxf(y[26], y[27]));
        float e0 = expf(y[25] - icm), e1 = expf(y[26] - icm), e2 = expf(y[27] - icm);
        float is = e0 + e1 + e2;
        float dcm = fmaxf(y[28], fmaxf(y[29], y[30]));
        float d0 = expf(y[28] - dcm), d1 = expf(y[29] - dcm), d2 = expf(y[30] - dcm);
        float ds = d0 + d1 + d2;
        op[0] = fetch;
        for (int i = 0; i < 11; i++) op[1 + i] = y[i];
        op[12] = fc_reg;
        op[13] = execc;
        for (int i = 0; i < 11; i++) op[14 + i] = y[12 + i];
        op[25] = ec_reg;
        op[26] = bm;
        op[27] = e0 / is; op[28] = e1 / is; op[29] = e2 / is;
        op[30] = d0 / ds; op[31] = d1 / ds; op[32] = d2 / ds;
        op[33] = bm_log;
        op[34] = y[25]; op[35] = y[26]; op[36] = y[27];
        op[37] = y[28]; op[38] = y[29]; op[39] = y[30];
    }
}

// ---------------- launch ----------------
extern "C" void kernel_launch(void* const* d_in, const int* in_sizes, int n_in,
                              void* d_out, int out_size)
{
    const void*  x       = d_in[0];
    const float* emb     = (const float*)d_in[1];
    const float* reg_w   = (const float*)d_in[2];
    const float* reg_b   = (const float*)d_in[3];
    const float* br_w    = (const float*)d_in[4];
    const float* br_b    = (const float*)d_in[5];
    const float* sh_w    = (const float*)d_in[6];
    const float* sh_b    = (const float*)d_in[7];
    const float* inst_w  = (const float*)d_in[8];
    const float* inst_b  = (const float*)d_in[9];
    const float* enc_ln_w = (const float*)d_in[10];
    const float* enc_ln_b = (const float*)d_in[11];
    const float* qkv_w   = (const float*)d_in[12];
    const float* out_w   = (const float*)d_in[13];
    const float* out_b   = (const float*)d_in[14];
    const float* w1_w    = (const float*)d_in[15];
    const float* w1_b    = (const float*)d_in[16];
    const float* w3_w    = (const float*)d_in[17];
    const float* w3_b    = (const float*)d_in[18];
    const float* w2_w    = (const float*)d_in[19];
    const float* w2_b    = (const float*)d_in[20];
    const float* n1_w    = (const float*)d_in[21];
    const float* n2_w    = (const float*)d_in[22];
    const float* head_ln_w = (const float*)d_in[23];
    const float* head_ln_b = (const float*)d_in[24];
    const float* head_w  = (const float*)d_in[25];
    const float* head_b  = (const float*)d_in[26];
    float* out = (float*)d_out;

    void *p;
    cudaGetSymbolAddress(&p, g_cat_hi);  uint16_t* cat_hi = (uint16_t*)p;
    cudaGetSymbolAddress(&p, g_cat_lo);  uint16_t* cat_lo = (uint16_t*)p;
    cudaGetSymbolAddress(&p, g_h);       float* h = (float*)p;
    cudaGetSymbolAddress(&p, g_xn_hi);   uint16_t* xn_hi = (uint16_t*)p;
    cudaGetSymbolAddress(&p, g_xn_lo);   uint16_t* xn_lo = (uint16_t*)p;
    cudaGetSymbolAddress(&p, g_qkv);     float* qkv = (float*)p;
    cudaGetSymbolAddress(&p, g_att_hi);  uint16_t* att_hi = (uint16_t*)p;
    cudaGetSymbolAddress(&p, g_att_lo);  uint16_t* att_lo = (uint16_t*)p;
    cudaGetSymbolAddress(&p, g_uf);      float* uf = (float*)p;
    cudaGetSymbolAddress(&p, g_u_hi);    uint16_t* u_hi = (uint16_t*)p;
    cudaGetSymbolAddress(&p, g_u_lo);    uint16_t* u_lo = (uint16_t*)p;
    cudaGetSymbolAddress(&p, g_w2p);     float* w2p = (float*)p;
    cudaGetSymbolAddress(&p, g_whi);     uint16_t* whi = (uint16_t*)p;
    cudaGetSymbolAddress(&p, g_wlo);     uint16_t* wlo = (uint16_t*)p;
    cudaGetSymbolAddress(&p, g_ropec);   float* ropec = (float*)p;
    cudaGetSymbolAddress(&p, g_ropes);   float* ropes = (float*)p;

    cudaFuncSetAttribute(attn_k, cudaFuncAttributeMaxDynamicSharedMemorySize, 131072);
    cudaFuncSetAttribute(tgemm_k, cudaFuncAttributeMaxDynamicSharedMemorySize, TG_DSMEM);

    detect_k<<<1, 1>>>((const int*)x);
    embed_k<<<NTOK, 192>>>(x, emb, reg_w, reg_b, br_w, br_b, sh_w, sh_b, cat_hi, cat_lo);
    padw2_k<<<1536, 256>>>(w2_w, w2p);
    ropetab_k<<<LSEQ, 32>>>(ropec, ropes);

    splitw_k<<<1024, 256>>>(inst_w, whi + OFF_INST, wlo + OFF_INST, CNT_INST);
    splitw_k<<<2048, 256>>>(qkv_w,  whi + OFF_QKV,  wlo + OFF_QKV,  CNT_QKV);
    splitw_k<<<1024, 256>>>(out_w,  whi + OFF_OUT,  wlo + OFF_OUT,  CNT_OUT);
    splitw_k<<<2048, 256>>>(w1_w,   whi + OFF_W1,   wlo + OFF_W1,   CNT_W1);
    splitw_k<<<2048, 256>>>(w3_w,   whi + OFF_W3,   wlo + OFF_W3,   CNT_W3);
    splitw_k<<<2048, 256>>>(w2p,    whi + OFF_W2,   wlo + OFF_W2,   CNT_W2);

    // encoder: h = silu(cat) @ inst_w.T + inst_b
    tgemm_k<<<dim3(4, 64), 256, TG_DSMEM>>>(cat_hi, cat_lo, 768,
                                            whi + OFF_INST, wlo + OFF_INST, 768,
                                            inst_b, nullptr, nullptr,
                                            h, nullptr, nullptr, 512, 512, 768);
    lnsilu_k<<<NTOK, 128>>>(h, enc_ln_w, enc_ln_b);

    for (int l = 0; l < 3; l++) {
        rms_k<<<NTOK, 128>>>(h, n1_w + l * 512, xn_hi, xn_lo);
        tgemm_k<<<dim3(12, 64), 256, TG_DSMEM>>>(xn_hi, xn_lo, 512,
                                                 whi + OFF_QKV + (size_t)l * 1536 * 512,
                                                 wlo + OFF_QKV + (size_t)l * 1536 * 512, 512,
                                                 nullptr, nullptr, nullptr,
                                                 qkv, nullptr, nullptr, 1536, 1536, 512);
        attn_k<<<dim3(16, 8, 4), 256, 131072>>>(qkv, ropec, ropes, att_hi, att_lo);
        tgemm_k<<<dim3(4, 64), 256, TG_DSMEM>>>(att_hi, att_lo, 512,
                                                whi + OFF_OUT + (size_t)l * 512 * 512,
                                                wlo + OFF_OUT + (size_t)l * 512 * 512, 512,
                                                out_b + l * 512, h, nullptr,
                                                h, nullptr, nullptr, 512, 512, 512);
        rms_k<<<NTOK, 128>>>(h, n2_w + l * 512, xn_hi, xn_lo);
        tgemm_k<<<dim3(11, 64), 256, TG_DSMEM>>>(xn_hi, xn_lo, 512,
                                                 whi + OFF_W1 + (size_t)l * DFF * 512,
                                                 wlo + OFF_W1 + (size_t)l * DFF * 512, 512,
                                                 w1_b + l * DFF, nullptr, nullptr,
                                                 uf, nullptr, nullptr, DFFP, DFF, 512);
        tgemm_k<<<dim3(11, 64), 256, TG_DSMEM>>>(xn_hi, xn_lo, 512,
                                                 whi + OFF_W3 + (size_t)l * DFF * 512,
                                                 wlo + OFF_W3 + (size_t)l * DFF * 512, 512,
                                                 w3_b + l * DFF, nullptr, uf,
                                                 nullptr, u_hi, u_lo, DFFP, DFF, 512);
        tgemm_k<<<dim3(4, 64), 256, TG_DSMEM>>>(u_hi, u_lo, DFFP,
                                                whi + OFF_W2 + (size_t)l * 512 * DFFP,
                                                wlo + OFF_W2 + (size_t)l * 512 * DFFP, DFFP,
                                                w2_b + l * 512, h, nullptr,
                                                h, nullptr, nullptr, 512, 512, 1376);
    }

    head_k<<<NTOK, 256>>>(h, head_ln_w, head_ln_b, head_w, head_b, out);
}

// round 15
// speedup vs baseline: 1.2411x; 1.0701x over previous
#include <cuda_runtime.h>
#include <cuda_fp16.h>
#include <cstdint>
#include <cstddef>

#define NTOK 8192
#define LSEQ 2048
#define DMODEL 512
#define DFF 1365
#define DFFP 1376

// weight-plane offsets (fp16 elements)
#define OFF_INST 0
#define CNT_INST (512 * 768)
#define OFF_QKV  (OFF_INST + CNT_INST)
#define CNT_QKV  (3 * 1536 * 512)
#define OFF_OUT  (OFF_QKV + CNT_QKV)
#define CNT_OUT  (3 * 512 * 512)
#define OFF_W1   (OFF_OUT + CNT_OUT)
#define CNT_W1   (3 * DFF * 512)
#define OFF_W3   (OFF_W1 + CNT_W1)
#define CNT_W3   (3 * DFF * 512)
#define OFF_W2   (OFF_W3 + CNT_W3)
#define CNT_W2   (3 * 512 * DFFP)
#define WTOT     (OFF_W2 + CNT_W2)

#define WSCALE   64.0f
#define WUNSCALE 0.015625f

// ---------------- scratch (device globals; allocation-free) ----------------
__device__ __align__(16) uint16_t g_cat_hi[NTOK * 768];
__device__ __align__(16) uint16_t g_cat_lo[NTOK * 768];
__device__ __align__(16) float    g_h[NTOK * 512];
__device__ __align__(16) uint16_t g_xn_hi[NTOK * 512];
__device__ __align__(16) uint16_t g_xn_lo[NTOK * 512];
__device__ __align__(16) float    g_qkv[NTOK * 1536];
__device__ __align__(16) uint16_t g_att_hi[NTOK * 512];
__device__ __align__(16) uint16_t g_att_lo[NTOK * 512];
__device__ __align__(16) float    g_uf[NTOK * DFFP];      // w1 output (pads never read)
__device__ __align__(16) uint16_t g_u_hi[NTOK * DFFP];    // pads stay 0 (static zero init)
__device__ __align__(16) uint16_t g_u_lo[NTOK * DFFP];
__device__ __align__(16) float    g_w2p[3 * 512 * DFFP];
__device__ __align__(16) uint16_t g_whi[WTOT];
__device__ __align__(16) uint16_t g_wlo[WTOT];
__device__ __align__(16) float    g_ropec[LSEQ * 32];
__device__ __align__(16) float    g_ropes[LSEQ * 32];
__device__ int g_is64;

// ---------------- helpers ----------------
__device__ __forceinline__ uint32_t smem_u32(const void* p) {
    uint32_t a;
    asm("{ .reg .u64 t; cvta.to.shared.u64 t, %1; cvt.u32.u64 %0, t; }" : "=r"(a) : "l"(p));
    return a;
}
__device__ __forceinline__ void split2h(float x, uint16_t& h, uint16_t& l) {
    __half hh = __float2half_rn(x);
    __half ll = __float2half_rn(x - __half2float(hh));
    h = __half_as_ushort(hh);
    l = __half_as_ushort(ll);
}
__device__ __forceinline__ void mma_f16(float* d, const uint32_t* a, uint32_t b0, uint32_t b1) {
    asm volatile(
        "mma.sync.aligned.m16n8k16.row.col.f32.f16.f16.f32 "
        "{%0,%1,%2,%3}, {%4,%5,%6,%7}, {%8,%9}, {%0,%1,%2,%3};"
        : "+f"(d[0]), "+f"(d[1]), "+f"(d[2]), "+f"(d[3])
        : "r"(a[0]), "r"(a[1]), "r"(a[2]), "r"(a[3]), "r"(b0), "r"(b1));
}
__device__ __forceinline__ void cpasync16(uint32_t dst, const void* src) {
    asm volatile("cp.async.cg.shared.global [%0], [%1], 16;" :: "r"(dst), "l"(src) : "memory");
}

// ---------------- dtype probe for x (int64 vs int32) ----------------
__global__ void detect_k(const int* x) {
    long long s = 0;
    for (int i = 1; i < 8192; i += 2) { int v = x[i]; s += (v < 0) ? -(long long)v : (long long)v; }
    g_is64 = (s == 0) ? 1 : 0;
}

// ---------------- rope tables (bitwise-identical to in-kernel sincosf) ----------------
__global__ void ropetab_k(float* rc, float* rs) {
    int p = blockIdx.x, d2 = threadIdx.x;
    float inv = expf((float)d2 * -0.28782313662425572f);
    float sn, cs;
    sincosf((float)p * inv, &sn, &cs);
    rc[p * 32 + d2] = cs;
    rs[p * 32 + d2] = sn;
}

// ---------------- split weights (scaled by 64) into fp16 hi/lo planes ----------------
__global__ void splitw_k(const float* __restrict__ src, uint16_t* __restrict__ hi,
                         uint16_t* __restrict__ lo, int n)
{
    int stride = gridDim.x * 256;
    for (int i = blockIdx.x * 256 + threadIdx.x; i < n; i += stride) {
        uint16_t h, l;
        split2h(src[i] * WSCALE, h, l);
        hi[i] = h; lo[i] = l;
    }
}

// ---------------- pad w2 (3,512,1365) -> (3,512,1376) ----------------
__global__ void padw2_k(const float* __restrict__ w2, float* __restrict__ o)
{
    int row = blockIdx.x;  // 0..1535
    const float* src = w2 + (size_t)row * DFF;
    float* dst = o + (size_t)row * DFFP;
    for (int k = threadIdx.x; k < DFFP; k += 256) dst[k] = (k < DFF) ? src[k] : 0.f;
}

// ---------------- embed + input projections + silu (split output) ----------------
__global__ __launch_bounds__(192) void embed_k(
    const void* __restrict__ xraw,
    const float* __restrict__ emb,
    const float* __restrict__ reg_w, const float* __restrict__ reg_b,
    const float* __restrict__ br_w,  const float* __restrict__ br_b,
    const float* __restrict__ sh_w,  const float* __restrict__ sh_b,
    uint16_t* __restrict__ chi, uint16_t* __restrict__ clo)
{
    int m = blockIdx.x;
    int t = threadIdx.x;
    __shared__ float vals[288];
    __shared__ int tok_s;
    if (g_is64) {
        const long long* xr = (const long long*)xraw + (size_t)m * 289;
        if (t == 0) tok_s = (int)xr[0];
        for (int i = t; i < 288; i += 192) vals[i] = (float)xr[1 + i];
    } else {
        const int* xr = (const int*)xraw + (size_t)m * 289;
        if (t == 0) tok_s = xr[0];
        for (int i = t; i < 288; i += 192) vals[i] = (float)xr[1 + i];
    }
    __syncthreads();
    int tok = tok_s;
    float c0 = emb[(size_t)tok * 192 + t];
    float c1 = reg_b[t];
    const float* rw = reg_w + (size_t)t * 64;
#pragma unroll 8
    for (int k = 0; k < 64; k++) c1 = fmaf(vals[k], rw[k], c1);
    float c2 = br_b[t];
    const float* bw = br_w + (size_t)t * 32;
#pragma unroll 8
    for (int k = 0; k < 32; k++) c2 = fmaf(vals[256 + k], bw[k], c2);
    float c3 = sh_b[t];
    const float* sw = sh_w + (size_t)t * 192;
#pragma unroll 8
    for (int k = 0; k < 192; k++) c3 = fmaf(vals[64 + k], sw[k], c3);
    float s0 = c0 / (1.f + expf(-c0));
    float s1 = c1 / (1.f + expf(-c1));
    float s2 = c2 / (1.f + expf(-c2));
    float s3 = c3 / (1.f + expf(-c3));
    size_t base = (size_t)m * 768;
    uint16_t h, l;
    split2h(s0, h, l); chi[base + t] = h;        clo[base + t] = l;
    split2h(s1, h, l); chi[base + 192 + t] = h;  clo[base + 192 + t] = l;
    split2h(s2, h, l); chi[base + 384 + t] = h;  clo[base + 384 + t] = l;
    split2h(s3, h, l); chi[base + 576 + t] = h;  clo[base + 576 + t] = l;
}

// ---------------- 3xFP16 GEMM: pre-split fp16 hi/lo planes, cp.async, scalar frags ----------------
#define TSTRIDE 40
#define PS (128 * TSTRIDE)
#define TG_DSMEM (2 * 4 * PS * 2)

__global__ __launch_bounds__(256, 2) void tgemm_k(
    const uint16_t* __restrict__ Ahg, const uint16_t* __restrict__ Alg, int lda,
    const uint16_t* __restrict__ Whg, const uint16_t* __restrict__ Wlg, int ldw,
    const float* __restrict__ bias, const float* __restrict__ resid,
    const float* __restrict__ gate,
    float* __restrict__ C, uint16_t* __restrict__ Chi, uint16_t* __restrict__ Clo,
    int ldc, int N, int K)
{
    extern __shared__ uint16_t dsm[];
    const uint32_t sb = smem_u32(dsm);

    const int tid = threadIdx.x;
    const int wid = tid >> 5, lane = tid & 31;
    const int wm = wid >> 2, wn = wid & 3;
    const int gid = lane >> 2, tig = lane & 3;

    const int bm = blockIdx.y * 128, bn = blockIdx.x * 128;

    const int lrow = tid >> 1, lsub = (tid & 1) * 16;
    const uint16_t* Agh = Ahg + (size_t)(bm + lrow) * lda;
    const uint16_t* Agl = Alg + (size_t)(bm + lrow) * lda;
    const int wrow = bn + lrow;
    const int wsafe = (wrow < N) ? wrow : 0;
    const uint16_t* Wgh = Whg + (size_t)wsafe * ldw;
    const uint16_t* Wgl = Wlg + (size_t)wsafe * ldw;

    const uint32_t dbase = sb + 2 * (uint32_t)(lrow * TSTRIDE + lsub);

    float acc[4][4][4];
#pragma unroll
    for (int i = 0; i < 4; i++)
#pragma unroll
        for (int j = 0; j < 4; j++)
#pragma unroll
            for (int e = 0; e < 4; e++) acc[i][j][e] = 0.f;

    const int NC = K >> 5;

#define ISSUE(c, buf)                                                        \
    do {                                                                     \
        const int ke = (c) * 32 + lsub;                                      \
        uint32_t d = dbase + (uint32_t)(buf) * (4 * PS * 2);                 \
        cpasync16(d, Agh + ke);               cpasync16(d + 16, Agh + ke + 8);\
        cpasync16(d + PS * 2, Agl + ke);      cpasync16(d + PS * 2 + 16, Agl + ke + 8);\
        cpasync16(d + 2 * PS * 2, Wgh + ke);  cpasync16(d + 2 * PS * 2 + 16, Wgh + ke + 8);\
        cpasync16(d + 3 * PS * 2, Wgl + ke);  cpasync16(d + 3 * PS * 2 + 16, Wgl + ke + 8);\
        asm volatile("cp.async.commit_group;" ::: "memory");                 \
    } while (0)

    ISSUE(0, 0);

    for (int c = 0; c < NC; c++) {
        const int buf = c & 1;
        if (c + 1 < NC) {
            ISSUE(c + 1, (c + 1) & 1);
            asm volatile("cp.async.wait_group 1;" ::: "memory");
        } else {
            asm volatile("cp.async.wait_group 0;" ::: "memory");
        }
        __syncthreads();

        const uint16_t* Ah = dsm + buf * 4 * PS;
        const uint16_t* Al = Ah + PS;
        const uint16_t* Bh = Ah + 2 * PS;
        const uint16_t* Bl = Ah + 3 * PS;
#pragma unroll
        for (int s = 0; s < 2; s++) {
            const int kk = s * 16 + 2 * tig;
            uint32_t bh[4][2], bl[4][2];
#pragma unroll
            for (int nt = 0; nt < 4; nt++) {
                const int n0 = (wn * 32 + nt * 8 + gid) * TSTRIDE + kk;
                bh[nt][0] = *(const uint32_t*)(Bh + n0);
                bh[nt][1] = *(const uint32_t*)(Bh + n0 + 8);
                bl[nt][0] = *(const uint32_t*)(Bl + n0);
                bl[nt][1] = *(const uint32_t*)(Bl + n0 + 8);
            }
#pragma unroll
            for (int mt = 0; mt < 4; mt++) {
                const int r0 = (wm * 64 + mt * 16 + gid) * TSTRIDE + kk;
                const int r1 = r0 + 8 * TSTRIDE;
                uint32_t ah[4], al[4];
                ah[0] = *(const uint32_t*)(Ah + r0); ah[1] = *(const uint32_t*)(Ah + r1);
                ah[2] = *(const uint32_t*)(Ah + r0 + 8); ah[3] = *(const uint32_t*)(Ah + r1 + 8);
                al[0] = *(const uint32_t*)(Al + r0); al[1] = *(const uint32_t*)(Al + r1);
                al[2] = *(const uint32_t*)(Al + r0 + 8); al[3] = *(const uint32_t*)(Al + r1 + 8);
#pragma unroll
                for (int nt = 0; nt < 4; nt++)
                    mma_f16(acc[mt][nt], ah, bh[nt][0], bh[nt][1]);
#pragma unroll
                for (int nt = 0; nt < 4; nt++)
                    mma_f16(acc[mt][nt], ah, bl[nt][0], bl[nt][1]);
#pragma unroll
                for (int nt = 0; nt < 4; nt++)
                    mma_f16(acc[mt][nt], al, bh[nt][0], bh[nt][1]);
            }
        }
        __syncthreads();
    }

    // epilogue (unscale weights by 1/64 first)
#pragma unroll
    for (int mt = 0; mt < 4; mt++) {
        const int grow = bm + wm * 64 + mt * 16 + gid;
        const size_t r0o = (size_t)grow * ldc, r1o = (size_t)(grow + 8) * ldc;
#pragma unroll
        for (int nt = 0; nt < 4; nt++) {
            const int gcol = bn + wn * 32 + nt * 8 + tig * 2;
#pragma unroll
            for (int half = 0; half < 2; half++) {
                const int cc = gcol + half;
                if (cc >= N) continue;
                const size_t i0 = r0o + cc, i1 = r1o + cc;
                float v0 = acc[mt][nt][half] * WUNSCALE;
                float v1 = acc[mt][nt][2 + half] * WUNSCALE;
                if (bias) { const float b = bias[cc]; v0 += b; v1 += b; }
                if (gate) {
                    const float gv0 = gate[i0], gv1 = gate[i1];
                    v0 *= gv0 / (1.f + expf(-gv0));
                    v1 *= gv1 / (1.f + expf(-gv1));
                }
                if (resid) { v0 += resid[i0]; v1 += resid[i1]; }
                if (C) { C[i0] = v0; C[i1] = v1; }
                if (Chi) {
                    uint16_t h, l;
                    split2h(v0, h, l); Chi[i0] = h; Clo[i0] = l;
                    split2h(v1, h, l); Chi[i1] = h; Clo[i1] = l;
                }
            }
        }
    }
}

// ---------------- RMSNorm (split output) ----------------
__global__ __launch_bounds__(128) void rms_k(
    const float* __restrict__ h, const float* __restrict__ w,
    uint16_t* __restrict__ ohi, uint16_t* __restrict__ olo)
{
    int m = blockIdx.x, t = threadIdx.x;
    const float4* hr = (const float4*)(h + (size_t)m * 512);
    float4 v = hr[t];
    float ss = v.x * v.x + v.y * v.y + v.z * v.z + v.w * v.w;
#pragma unroll
    for (int off = 16; off; off >>= 1) ss += __shfl_down_sync(0xffffffffu, ss, off);
    __shared__ float red[4];
    __shared__ float sc_s;
    if ((t & 31) == 0) red[t >> 5] = ss;
    __syncthreads();
    if (t == 0) sc_s = rsqrtf((red[0] + red[1] + red[2] + red[3]) / 512.f + 1.1920929e-07f);
    __syncthreads();
    float sc = sc_s;
    float4 wv = ((const float4*)w)[t];
    float r0 = v.x * sc * wv.x, r1 = v.y * sc * wv.y, r2 = v.z * sc * wv.z, r3 = v.w * sc * wv.w;
    ushort4 hh, ll;
    split2h(r0, hh.x, ll.x); split2h(r1, hh.y, ll.y);
    split2h(r2, hh.z, ll.z); split2h(r3, hh.w, ll.w);
    ((ushort4*)(ohi + (size_t)m * 512))[t] = hh;
    ((ushort4*)(olo + (size_t)m * 512))[t] = ll;
}

// ---------------- LayerNorm + SiLU (in place, float) ----------------
__global__ __launch_bounds__(128) void lnsilu_k(
    float* __restrict__ h, const float* __restrict__ w, const float* __restrict__ b)
{
    int m = blockIdx.x, t = threadIdx.x;
    float4* hr = (float4*)(h + (size_t)m * 512);
    float4 v = hr[t];
    float s1 = v.x + v.y + v.z + v.w;
    float s2 = v.x * v.x + v.y * v.y + v.z * v.z + v.w * v.w;
#pragma unroll
    for (int off = 16; off; off >>= 1) {
        s1 += __shfl_down_sync(0xffffffffu, s1, off);
        s2 += __shfl_down_sync(0xffffffffu, s2, off);
    }
    __shared__ float red[8];
    __shared__ float st[2];
    if ((t & 31) == 0) { red[t >> 5] = s1; red[4 + (t >> 5)] = s2; }
    __syncthreads();
    if (t == 0) {
        float a = red[0] + red[1] + red[2] + red[3];
        float q = red[4] + red[5] + red[6] + red[7];
        float mean = a / 512.f;
        float var = q / 512.f - mean * mean;
        st[0] = mean; st[1] = rsqrtf(var + 1e-5f);
    }
    __syncthreads();
    float mean = st[0], rstd = st[1];
    float4 wv = ((const float4*)w)[t], bv = ((const float4*)b)[t];
    float x0 = (v.x - mean) * rstd * wv.x + bv.x;
    float x1 = (v.y - mean) * rstd * wv.y + bv.y;
    float x2 = (v.z - mean) * rstd * wv.z + bv.z;
    float x3 = (v.w - mean) * rstd * wv.w + bv.w;
    float4 r;
    r.x = x0 / (1.f + expf(-x0)); r.y = x1 / (1.f + expf(-x1));
    r.z = x2 / (1.f + expf(-x2)); r.w = x3 / (1.f + expf(-x3));
    hr[t] = r;
}

// ---------------- sliding-window attention (rope tables + warp-trimmed j loop) ----------------
__global__ __launch_bounds__(256) void attn_k(const float* __restrict__ qkv,
                                              const float* __restrict__ rc,
                                              const float* __restrict__ rs,
                                              uint16_t* __restrict__ ohi,
                                              uint16_t* __restrict__ olo)
{
    extern __shared__ float sm[];
    float* Ks = sm;            // 256 x 64
    float* Vs = sm + 16384;    // 256 x 64
    const int n = blockIdx.x, hh = blockIdx.y, b = blockIdx.z;
    const int tid = threadIdx.x;

    {
        int d2 = tid & 31, j0 = tid >> 5;
        for (int j = j0; j < 256; j += 8) {
            int p = (n - 1) * 128 + j;
            if (p >= 0) {
                size_t base = ((size_t)(b * LSEQ + p)) * 1536 + hh * 192 + d2 * 6;
                float k0 = qkv[base + 1], k1 = qkv[base + 4];
                float v0 = qkv[base + 2], v1 = qkv[base + 5];
                float cs = rc[p * 32 + d2], sn = rs[p * 32 + d2];
                Ks[j * 64 + 2 * d2]     = k0 * cs - k1 * sn;
                Ks[j * 64 + 2 * d2 + 1] = k0 * sn + k1 * cs;
                Vs[j * 64 + 2 * d2]     = v0;
                Vs[j * 64 + 2 * d2 + 1] = v1;
            } else {
                Ks[j * 64 + 2 * d2] = 0.f; Ks[j * 64 + 2 * d2 + 1] = 0.f;
                Vs[j * 64 + 2 * d2] = 0.f; Vs[j * 64 + 2 * d2 + 1] = 0.f;
            }
        }
    }
    const int qi = tid >> 1, half = tid & 1;
    const int pq = n * 128 + qi;
    float q[32];
    {
        size_t base = ((size_t)(b * LSEQ + pq)) * 1536 + hh * 192;
#pragma unroll
        for (int t = 0; t < 16; t++) {
            int d2 = half * 16 + t;
            float q0 = qkv[base + d2 * 6], q1 = qkv[base + d2 * 6 + 3];
            float cs = rc[pq * 32 + d2], sn = rs[pq * 32 + d2];
            q[2 * t]     = q0 * cs - q1 * sn;
            q[2 * t + 1] = q0 * sn + q1 * cs;
        }
    }
    __syncthreads();

    const int jstart = (n == 0) ? 128 : qi;
    const int jend = qi + 128;
    // warp-uniform loop bounds: warp covers qi in [16w, 16w+15]
    const int wqi = (tid >> 5) * 16;   // qi base for this warp (tid>>1 -> qi; 32 thr = 16 qi)
    const int jlo = (n == 0) ? 128 : wqi;
    const int jhi = wqi + 15 + 128;    // inclusive

    float mx = -1e30f;
    for (int j = jlo; j <= jhi; j++) {
        const float4* kr = (const float4*)(Ks + j * 64 + half * 32);
        float s = 0.f;
#pragma unroll
        for (int t = 0; t < 8; t++) {
            float4 kv = kr[t];
            s = fmaf(q[4 * t], kv.x, s); s = fmaf(q[4 * t + 1], kv.y, s);
            s = fmaf(q[4 * t + 2], kv.z, s); s = fmaf(q[4 * t + 3], kv.w, s);
        }
        s += __shfl_xor_sync(0xffffffffu, s, 1);
        if (j >= jstart && j <= jend) mx = fmaxf(mx, s);
    }
    float l = 0.f;
    float o[32];
#pragma unroll
    for (int t = 0; t < 32; t++) o[t] = 0.f;
    for (int j = jlo; j <= jhi; j++) {
        const float4* kr = (const float4*)(Ks + j * 64 + half * 32);
        float s = 0.f;
#pragma unroll
        for (int t = 0; t < 8; t++) {
            float4 kv = kr[t];
            s = fmaf(q[4 * t], kv.x, s); s = fmaf(q[4 * t + 1], kv.y, s);
            s = fmaf(q[4 * t + 2], kv.z, s); s = fmaf(q[4 * t + 3], kv.w, s);
        }
        s += __shfl_xor_sync(0xffffffffu, s, 1);
        if (j >= jstart && j <= jend) {
            float p = __expf((s - mx) * 0.125f);
            l += p;
            const float4* vr = (const float4*)(Vs + j * 64 + half * 32);
#pragma unroll
            for (int t = 0; t < 8; t++) {
                float4 vv = vr[t];
                o[4 * t]     = fmaf(p, vv.x, o[4 * t]);
                o[4 * t + 1] = fmaf(p, vv.y, o[4 * t + 1]);
                o[4 * t + 2] = fmaf(p, vv.z, o[4 * t + 2]);
                o[4 * t + 3] = fmaf(p, vv.w, o[4 * t + 3]);
            }
        }
    }
    float invl = 1.f / l;
    size_t obase = ((size_t)(b * LSEQ + pq)) * 512 + hh * 64 + half * 32;
#pragma unroll
    for (int t = 0; t < 8; t++) {
        ushort4 hh4, ll4;
        split2h(o[4 * t] * invl,     hh4.x, ll4.x);
        split2h(o[4 * t + 1] * invl, hh4.y, ll4.y);
        split2h(o[4 * t + 2] * invl, hh4.z, ll4.z);
        split2h(o[4 * t + 3] * invl, hh4.w, ll4.w);
        ((ushort4*)(ohi + obase))[t] = hh4;
        ((ushort4*)(olo + obase))[t] = ll4;
    }
}

// ---------------- head: LN+SiLU, 31-dim projection, postprocess ----------------
__device__ __forceinline__ float softplus_f(float x) { return x > 20.f ? x : log1pf(expf(x)); }

__global__ __launch_bounds__(256) void head_k(
    const float* __restrict__ h,
    const float* __restrict__ lw, const float* __restrict__ lb,
    const float* __restrict__ hw, const float* __restrict__ hb,
    float* __restrict__ out)
{
    int m = blockIdx.x, t = threadIdx.x;
    __shared__ float xs[512];
    __shared__ float red[16];
    __shared__ float ysh[31];
    __shared__ float st[2];
    const float* hr = h + (size_t)m * 512;
    float a = hr[t], b2 = hr[t + 256];
    float s1 = a + b2, s2 = a * a + b2 * b2;
#pragma unroll
    for (int off = 16; off; off >>= 1) {
        s1 += __shfl_down_sync(0xffffffffu, s1, off);
        s2 += __shfl_down_sync(0xffffffffu, s2, off);
    }
    if ((t & 31) == 0) { red[t >> 5] = s1; red[8 + (t >> 5)] = s2; }
    __syncthreads();
    if (t == 0) {
        float ss1 = 0.f, ss2 = 0.f;
        for (int i = 0; i < 8; i++) { ss1 += red[i]; ss2 += red[8 + i]; }
        float mean = ss1 / 512.f;
        float var = ss2 / 512.f - mean * mean;
        st[0] = mean; st[1] = rsqrtf(var + 1e-5f);
    }
    __syncthreads();
    float mean = st[0], rstd = st[1];
    float va = (a - mean) * rstd * lw[t] + lb[t];
    float vb = (b2 - mean) * rstd * lw[t + 256] + lb[t + 256];
    xs[t] = va / (1.f + expf(-va));
    xs[t + 256] = vb / (1.f + expf(-vb));
    __syncthreads();
    {
        int nn = t >> 3, p = t & 7;
        bool valid = nn < 31;
        const float* wr = hw + (size_t)(valid ? nn : 0) * 512;
        float acc = 0.f;
#pragma unroll 8
        for (int kk = 0; kk < 64; kk++) {
            int k = kk * 8 + p;
            acc = fmaf(xs[k], wr[k], acc);
        }
        acc += __shfl_down_sync(0xffffffffu, acc, 4, 8);
        acc += __shfl_down_sync(0xffffffffu, acc, 2, 8);
        acc += __shfl_down_sync(0xffffffffu, acc, 1, 8);
        if (valid && p == 0) ysh[nn] = acc + hb[nn];
    }
    __syncthreads();
    if (t == 0) {
        float y[31];
#pragma unroll
        for (int i = 0; i < 31; i++) y[i] = ysh[i];
        float* op = out + (size_t)m * 40;
        int am = 0;
        for (int i = 1; i < 11; i++) if (y[i] > y[am]) am = i;
        float fc_reg = softplus_f(y[11]);
        float fetch = (am < 10) ? (float)(am + 1) : fc_reg;
        int ae = 0;
        for (int i = 1; i < 11; i++) if (y[12 + i] > y[12 + ae]) ae = i;
        float ec_reg = softplus_f(y[23]);
        float execc = (ae < 10) ? (float)(ae + 1) : ec_reg;
        float bm_log = y[24];
        float bm = 1.f / (1.f + expf(-bm_log));
        float icm = fmaxf(y[25], fmaxf(y[26], y[27]));
        float e0 = expf(y[25] - icm), e1 = expf(y[26] - icm), e2 = expf(y[27] - icm);
        float is = e0 + e1 + e2;
        float dcm = fmaxf(y[28], fmaxf(y[29], y[30]));
        float d0 = expf(y[28] - dcm), d1 = expf(y[29] - dcm), d2 = expf(y[30] - dcm);
        float ds = d0 + d1 + d2;
        op[0] = fetch;
        for (int i = 0; i < 11; i++) op[1 + i] = y[i];
        op[12] = fc_reg;
        op[13] = execc;
        for (int i = 0; i < 11; i++) op[14 + i] = y[12 + i];
        op[25] = ec_reg;
        op[26] = bm;
        op[27] = e0 / is; op[28] = e1 / is; op[29] = e2 / is;
        op[30] = d0 / ds; op[31] = d1 / ds; op[32] = d2 / ds;
        op[33] = bm_log;
        op[34] = y[25]; op[35] = y[26]; op[36] = y[27];
        op[37] = y[28]; op[38] = y[29]; op[39] = y[30];
    }
}

// ---------------- launch ----------------
extern "C" void kernel_launch(void* const* d_in, const int* in_sizes, int n_in,
                              void* d_out, int out_size)
{
    const void*  x       = d_in[0];
    const float* emb     = (const float*)d_in[1];
    const float* reg_w   = (const float*)d_in[2];
    const float* reg_b   = (const float*)d_in[3];
    const float* br_w    = (const float*)d_in[4];
    const float* br_b    = (const float*)d_in[5];
    const float* sh_w    = (const float*)d_in[6];
    const float* sh_b    = (const float*)d_in[7];
    const float* inst_w  = (const float*)d_in[8];
    const float* inst_b  = (const float*)d_in[9];
    const float* enc_ln_w = (const float*)d_in[10];
    const float* enc_ln_b = (const float*)d_in[11];
    const float* qkv_w   = (const float*)d_in[12];
    const float* out_w   = (const float*)d_in[13];
    const float* out_b   = (const float*)d_in[14];
    const float* w1_w    = (const float*)d_in[15];
    const float* w1_b    = (const float*)d_in[16];
    const float* w3_w    = (const float*)d_in[17];
    const float* w3_b    = (const float*)d_in[18];
    const float* w2_w    = (const float*)d_in[19];
    const float* w2_b    = (const float*)d_in[20];
    const float* n1_w    = (const float*)d_in[21];
    const float* n2_w    = (const float*)d_in[22];
    const float* head_ln_w = (const float*)d_in[23];
    const float* head_ln_b = (const float*)d_in[24];
    const float* head_w  = (const float*)d_in[25];
    const float* head_b  = (const float*)d_in[26];
    float* out = (float*)d_out;

    void *p;
    cudaGetSymbolAddress(&p, g_cat_hi);  uint16_t* cat_hi = (uint16_t*)p;
    cudaGetSymbolAddress(&p, g_cat_lo);  uint16_t* cat_lo = (uint16_t*)p;
    cudaGetSymbolAddress(&p, g_h);       float* h = (float*)p;
    cudaGetSymbolAddress(&p, g_xn_hi);   uint16_t* xn_hi = (uint16_t*)p;
    cudaGetSymbolAddress(&p, g_xn_lo);   uint16_t* xn_lo = (uint16_t*)p;
    cudaGetSymbolAddress(&p, g_qkv);     float* qkv = (float*)p;
    cudaGetSymbolAddress(&p, g_att_hi);  uint16_t* att_hi = (uint16_t*)p;
    cudaGetSymbolAddress(&p, g_att_lo);  uint16_t* att_lo = (uint16_t*)p;
    cudaGetSymbolAddress(&p, g_uf);      float* uf = (float*)p;
    cudaGetSymbolAddress(&p, g_u_hi);    uint16_t* u_hi = (uint16_t*)p;
    cudaGetSymbolAddress(&p, g_u_lo);    uint16_t* u_lo = (uint16_t*)p;
    cudaGetSymbolAddress(&p, g_w2p);     float* w2p = (float*)p;
    cudaGetSymbolAddress(&p, g_whi);     uint16_t* whi = (uint16_t*)p;
    cudaGetSymbolAddress(&p, g_wlo);     uint16_t* wlo = (uint16_t*)p;
    cudaGetSymbolAddress(&p, g_ropec);   float* ropec = (float*)p;
    cudaGetSymbolAddress(&p, g_ropes);   float* ropes = (float*)p;

    cudaFuncSetAttribute(attn_k, cudaFuncAttributeMaxDynamicSharedMemorySize, 131072);
    cudaFuncSetAttribute(tgemm_k, cudaFuncAttributeMaxDynamicSharedMemorySize, TG_DSMEM);

    detect_k<<<1, 1>>>((const int*)x);
    embed_k<<<NTOK, 192>>>(x, emb, reg_w, reg_b, br_w, br_b, sh_w, sh_b, cat_hi, cat_lo);
    padw2_k<<<1536, 256>>>(w2_w, w2p);
    ropetab_k<<<LSEQ, 32>>>(ropec, ropes);

    splitw_k<<<1024, 256>>>(inst_w, whi + OFF_INST, wlo + OFF_INST, CNT_INST);
    splitw_k<<<2048, 256>>>(qkv_w,  whi + OFF_QKV,  wlo + OFF_QKV,  CNT_QKV);
    splitw_k<<<1024, 256>>>(out_w,  whi + OFF_OUT,  wlo + OFF_OUT,  CNT_OUT);
    splitw_k<<<2048, 256>>>(w1_w,   whi + OFF_W1,   wlo + OFF_W1,   CNT_W1);
    splitw_k<<<2048, 256>>>(w3_w,   whi + OFF_W3,   wlo + OFF_W3,   CNT_W3);
    splitw_k<<<2048, 256>>>(w2p,    whi + OFF_W2,   wlo + OFF_W2,   CNT_W2);

    // encoder: h = silu(cat) @ inst_w.T + inst_b
    tgemm_k<<<dim3(4, 64), 256, TG_DSMEM>>>(cat_hi, cat_lo, 768,
                                            whi + OFF_INST, wlo + OFF_INST, 768,
                                            inst_b, nullptr, nullptr,
                                            h, nullptr, nullptr, 512, 512, 768);
    lnsilu_k<<<NTOK, 128>>>(h, enc_ln_w, enc_ln_b);

    for (int l = 0; l < 3; l++) {
        rms_k<<<NTOK, 128>>>(h, n1_w + l * 512, xn_hi, xn_lo);
        tgemm_k<<<dim3(12, 64), 256, TG_DSMEM>>>(xn_hi, xn_lo, 512,
                                                 whi + OFF_QKV + (size_t)l * 1536 * 512,
                                                 wlo + OFF_QKV + (size_t)l * 1536 * 512, 512,
                                                 nullptr, nullptr, nullptr,
                                                 qkv, nullptr, nullptr, 1536, 1536, 512);
        attn_k<<<dim3(16, 8, 4), 256, 131072>>>(qkv, ropec, ropes, att_hi, att_lo);
        tgemm_k<<<dim3(4, 64), 256, TG_DSMEM>>>(att_hi, att_lo, 512,
                                                whi + OFF_OUT + (size_t)l * 512 * 512,
                                                wlo + OFF_OUT + (size_t)l * 512 * 512, 512,
                                                out_b + l * 512, h, nullptr,
                                                h, nullptr, nullptr, 512, 512, 512);
        rms_k<<<NTOK, 128>>>(h, n2_w + l * 512, xn_hi, xn_lo);
        tgemm_k<<<dim3(11, 64), 256, TG_DSMEM>>>(xn_hi, xn_lo, 512,
                                                 whi + OFF_W1 + (size_t)l * DFF * 512,
                                                 wlo + OFF_W1 + (size_t)l * DFF * 512, 512,
                                                 w1_b + l * DFF, nullptr, nullptr,
                                                 uf, nullptr, nullptr, DFFP, DFF, 512);
        tgemm_k<<<dim3(11, 64), 256, TG_DSMEM>>>(xn_hi, xn_lo, 512,
                                                 whi + OFF_W3 + (size_t)l * DFF * 512,
                                                 wlo + OFF_W3 + (size_t)l * DFF * 512, 512,
                                                 w3_b + l * DFF, nullptr, uf,
                                                 nullptr, u_hi, u_lo, DFFP, DFF, 512);
        tgemm_k<<<dim3(4, 64), 256, TG_DSMEM>>>(u_hi, u_lo, DFFP,
                                                whi + OFF_W2 + (size_t)l * 512 * DFFP,
                                                wlo + OFF_W2 + (size_t)l * 512 * DFFP, DFFP,
                                                w2_b + l * 512, h, nullptr,
                                                h, nullptr, nullptr, 512, 512, 1376);
    }

    head_k<<<NTOK, 256>>>(h, head_ln_w, head_ln_b, head_w, head_b, out);
}

// round 16
// speedup vs baseline: 1.2952x; 1.0436x over previous
#include <cuda_runtime.h>
#include <cuda_fp16.h>
#include <cstdint>
#include <cstddef>

#define NTOK 8192
#define LSEQ 2048
#define DMODEL 512
#define DFF 1365
#define DFFP 1376

// weight-plane offsets (fp16 elements)
#define OFF_INST 0
#define CNT_INST (512 * 768)
#define OFF_QKV  (OFF_INST + CNT_INST)
#define CNT_QKV  (3 * 1536 * 512)
#define OFF_OUT  (OFF_QKV + CNT_QKV)
#define CNT_OUT  (3 * 512 * 512)
#define OFF_W1   (OFF_OUT + CNT_OUT)
#define CNT_W1   (3 * DFF * 512)
#define OFF_W3   (OFF_W1 + CNT_W1)
#define CNT_W3   (3 * DFF * 512)
#define OFF_W2   (OFF_W3 + CNT_W3)
#define CNT_W2   (3 * 512 * DFFP)
#define WTOT     (OFF_W2 + CNT_W2)

#define WSCALE   64.0f
#define WUNSCALE 0.015625f

// ---------------- scratch (device globals; allocation-free) ----------------
__device__ __align__(16) uint16_t g_cat_hi[NTOK * 768];
__device__ __align__(16) uint16_t g_cat_lo[NTOK * 768];
__device__ __align__(16) float    g_h[NTOK * 512];
__device__ __align__(16) uint16_t g_xn_hi[NTOK * 512];
__device__ __align__(16) uint16_t g_xn_lo[NTOK * 512];
__device__ __align__(16) float    g_qkv[NTOK * 1536];
__device__ __align__(16) uint16_t g_att_hi[NTOK * 512];
__device__ __align__(16) uint16_t g_att_lo[NTOK * 512];
__device__ __align__(16) float    g_uf[NTOK * DFFP];      // w1 output (pads never read)
__device__ __align__(16) uint16_t g_u_hi[NTOK * DFFP];    // pads stay 0 (static zero init)
__device__ __align__(16) uint16_t g_u_lo[NTOK * DFFP];
__device__ __align__(16) float    g_w2p[3 * 512 * DFFP];
__device__ __align__(16) uint16_t g_whi[WTOT];
__device__ __align__(16) uint16_t g_wlo[WTOT];
__device__ __align__(16) float    g_ropec[LSEQ * 32];
__device__ __align__(16) float    g_ropes[LSEQ * 32];
__device__ int g_is64;

// ---------------- helpers ----------------
__device__ __forceinline__ uint32_t smem_u32(const void* p) {
    uint32_t a;
    asm("{ .reg .u64 t; cvta.to.shared.u64 t, %1; cvt.u32.u64 %0, t; }" : "=r"(a) : "l"(p));
    return a;
}
__device__ __forceinline__ void split2h(float x, uint16_t& h, uint16_t& l) {
    __half hh = __float2half_rn(x);
    __half ll = __float2half_rn(x - __half2float(hh));
    h = __half_as_ushort(hh);
    l = __half_as_ushort(ll);
}
__device__ __forceinline__ void mma_f16(float* d, const uint32_t* a, uint32_t b0, uint32_t b1) {
    asm volatile(
        "mma.sync.aligned.m16n8k16.row.col.f32.f16.f16.f32 "
        "{%0,%1,%2,%3}, {%4,%5,%6,%7}, {%8,%9}, {%0,%1,%2,%3};"
        : "+f"(d[0]), "+f"(d[1]), "+f"(d[2]), "+f"(d[3])
        : "r"(a[0]), "r"(a[1]), "r"(a[2]), "r"(a[3]), "r"(b0), "r"(b1));
}
__device__ __forceinline__ void cpasync16(uint32_t dst, const void* src) {
    asm volatile("cp.async.cg.shared.global [%0], [%1], 16;" :: "r"(dst), "l"(src) : "memory");
}

// ---------------- dtype probe for x (int64 vs int32) ----------------
__global__ void detect_k(const int* x) {
    long long s = 0;
    for (int i = 1; i < 8192; i += 2) { int v = x[i]; s += (v < 0) ? -(long long)v : (long long)v; }
    g_is64 = (s == 0) ? 1 : 0;
}

// ---------------- rope tables (bitwise-identical to in-kernel sincosf) ----------------
__global__ void ropetab_k(float* rc, float* rs) {
    int p = blockIdx.x, d2 = threadIdx.x;
    float inv = expf((float)d2 * -0.28782313662425572f);
    float sn, cs;
    sincosf((float)p * inv, &sn, &cs);
    rc[p * 32 + d2] = cs;
    rs[p * 32 + d2] = sn;
}

// ---------------- split weights (scaled by 64) into fp16 hi/lo planes ----------------
__global__ void splitw_k(const float* __restrict__ src, uint16_t* __restrict__ hi,
                         uint16_t* __restrict__ lo, int n)
{
    int stride = gridDim.x * 256;
    for (int i = blockIdx.x * 256 + threadIdx.x; i < n; i += stride) {
        uint16_t h, l;
        split2h(src[i] * WSCALE, h, l);
        hi[i] = h; lo[i] = l;
    }
}

// ---------------- pad w2 (3,512,1365) -> (3,512,1376) ----------------
__global__ void padw2_k(const float* __restrict__ w2, float* __restrict__ o)
{
    int row = blockIdx.x;  // 0..1535
    const float* src = w2 + (size_t)row * DFF;
    float* dst = o + (size_t)row * DFFP;
    for (int k = threadIdx.x; k < DFFP; k += 256) dst[k] = (k < DFF) ? src[k] : 0.f;
}

// ---------------- embed + input projections + silu (split output) ----------------
__global__ __launch_bounds__(192) void embed_k(
    const void* __restrict__ xraw,
    const float* __restrict__ emb,
    const float* __restrict__ reg_w, const float* __restrict__ reg_b,
    const float* __restrict__ br_w,  const float* __restrict__ br_b,
    const float* __restrict__ sh_w,  const float* __restrict__ sh_b,
    uint16_t* __restrict__ chi, uint16_t* __restrict__ clo)
{
    int m = blockIdx.x;
    int t = threadIdx.x;
    __shared__ float vals[288];
    __shared__ int tok_s;
    if (g_is64) {
        const long long* xr = (const long long*)xraw + (size_t)m * 289;
        if (t == 0) tok_s = (int)xr[0];
        for (int i = t; i < 288; i += 192) vals[i] = (float)xr[1 + i];
    } else {
        const int* xr = (const int*)xraw + (size_t)m * 289;
        if (t == 0) tok_s = xr[0];
        for (int i = t; i < 288; i += 192) vals[i] = (float)xr[1 + i];
    }
    __syncthreads();
    int tok = tok_s;
    float c0 = emb[(size_t)tok * 192 + t];
    float c1 = reg_b[t];
    const float* rw = reg_w + (size_t)t * 64;
#pragma unroll 8
    for (int k = 0; k < 64; k++) c1 = fmaf(vals[k], rw[k], c1);
    float c2 = br_b[t];
    const float* bw = br_w + (size_t)t * 32;
#pragma unroll 8
    for (int k = 0; k < 32; k++) c2 = fmaf(vals[256 + k], bw[k], c2);
    float c3 = sh_b[t];
    const float* sw = sh_w + (size_t)t * 192;
#pragma unroll 8
    for (int k = 0; k < 192; k++) c3 = fmaf(vals[64 + k], sw[k], c3);
    float s0 = c0 / (1.f + expf(-c0));
    float s1 = c1 / (1.f + expf(-c1));
    float s2 = c2 / (1.f + expf(-c2));
    float s3 = c3 / (1.f + expf(-c3));
    size_t base = (size_t)m * 768;
    uint16_t h, l;
    split2h(s0, h, l); chi[base + t] = h;        clo[base + t] = l;
    split2h(s1, h, l); chi[base + 192 + t] = h;  clo[base + 192 + t] = l;
    split2h(s2, h, l); chi[base + 384 + t] = h;  clo[base + 384 + t] = l;
    split2h(s3, h, l); chi[base + 576 + t] = h;  clo[base + 576 + t] = l;
}

// ---------------- 3xFP16 GEMM: pre-split fp16 hi/lo planes, cp.async, scalar frags ----------------
#define TSTRIDE 40
#define PS (128 * TSTRIDE)
#define TG_DSMEM (2 * 4 * PS * 2)

__global__ __launch_bounds__(256, 2) void tgemm_k(
    const uint16_t* __restrict__ Ahg, const uint16_t* __restrict__ Alg, int lda,
    const uint16_t* __restrict__ Whg, const uint16_t* __restrict__ Wlg, int ldw,
    const float* __restrict__ bias, const float* __restrict__ resid,
    const float* __restrict__ gate,
    float* __restrict__ C, uint16_t* __restrict__ Chi, uint16_t* __restrict__ Clo,
    int ldc, int N, int K)
{
    extern __shared__ uint16_t dsm[];
    const uint32_t sb = smem_u32(dsm);

    const int tid = threadIdx.x;
    const int wid = tid >> 5, lane = tid & 31;
    const int wm = wid >> 2, wn = wid & 3;
    const int gid = lane >> 2, tig = lane & 3;

    const int bm = blockIdx.y * 128, bn = blockIdx.x * 128;

    const int lrow = tid >> 1, lsub = (tid & 1) * 16;
    const uint16_t* Agh = Ahg + (size_t)(bm + lrow) * lda;
    const uint16_t* Agl = Alg + (size_t)(bm + lrow) * lda;
    const int wrow = bn + lrow;
    const int wsafe = (wrow < N) ? wrow : 0;
    const uint16_t* Wgh = Whg + (size_t)wsafe * ldw;
    const uint16_t* Wgl = Wlg + (size_t)wsafe * ldw;

    const uint32_t dbase = sb + 2 * (uint32_t)(lrow * TSTRIDE + lsub);

    float acc[4][4][4];
#pragma unroll
    for (int i = 0; i < 4; i++)
#pragma unroll
        for (int j = 0; j < 4; j++)
#pragma unroll
            for (int e = 0; e < 4; e++) acc[i][j][e] = 0.f;

    const int NC = K >> 5;

#define ISSUE(c, buf)                                                        \
    do {                                                                     \
        const int ke = (c) * 32 + lsub;                                      \
        uint32_t d = dbase + (uint32_t)(buf) * (4 * PS * 2);                 \
        cpasync16(d, Agh + ke);               cpasync16(d + 16, Agh + ke + 8);\
        cpasync16(d + PS * 2, Agl + ke);      cpasync16(d + PS * 2 + 16, Agl + ke + 8);\
        cpasync16(d + 2 * PS * 2, Wgh + ke);  cpasync16(d + 2 * PS * 2 + 16, Wgh + ke + 8);\
        cpasync16(d + 3 * PS * 2, Wgl + ke);  cpasync16(d + 3 * PS * 2 + 16, Wgl + ke + 8);\
        asm volatile("cp.async.commit_group;" ::: "memory");                 \
    } while (0)

    ISSUE(0, 0);

    for (int c = 0; c < NC; c++) {
        const int buf = c & 1;
        if (c + 1 < NC) {
            ISSUE(c + 1, (c + 1) & 1);
            asm volatile("cp.async.wait_group 1;" ::: "memory");
        } else {
            asm volatile("cp.async.wait_group 0;" ::: "memory");
        }
        __syncthreads();

        const uint16_t* Ah = dsm + buf * 4 * PS;
        const uint16_t* Al = Ah + PS;
        const uint16_t* Bh = Ah + 2 * PS;
        const uint16_t* Bl = Ah + 3 * PS;
#pragma unroll
        for (int s = 0; s < 2; s++) {
            const int kk = s * 16 + 2 * tig;
            uint32_t bh[4][2], bl[4][2];
#pragma unroll
            for (int nt = 0; nt < 4; nt++) {
                const int n0 = (wn * 32 + nt * 8 + gid) * TSTRIDE + kk;
                bh[nt][0] = *(const uint32_t*)(Bh + n0);
                bh[nt][1] = *(const uint32_t*)(Bh + n0 + 8);
                bl[nt][0] = *(const uint32_t*)(Bl + n0);
                bl[nt][1] = *(const uint32_t*)(Bl + n0 + 8);
            }
#pragma unroll
            for (int mt = 0; mt < 4; mt++) {
                const int r0 = (wm * 64 + mt * 16 + gid) * TSTRIDE + kk;
                const int r1 = r0 + 8 * TSTRIDE;
                uint32_t ah[4], al[4];
                ah[0] = *(const uint32_t*)(Ah + r0); ah[1] = *(const uint32_t*)(Ah + r1);
                ah[2] = *(const uint32_t*)(Ah + r0 + 8); ah[3] = *(const uint32_t*)(Ah + r1 + 8);
                al[0] = *(const uint32_t*)(Al + r0); al[1] = *(const uint32_t*)(Al + r1);
                al[2] = *(const uint32_t*)(Al + r0 + 8); al[3] = *(const uint32_t*)(Al + r1 + 8);
#pragma unroll
                for (int nt = 0; nt < 4; nt++)
                    mma_f16(acc[mt][nt], ah, bh[nt][0], bh[nt][1]);
#pragma unroll
                for (int nt = 0; nt < 4; nt++)
                    mma_f16(acc[mt][nt], ah, bl[nt][0], bl[nt][1]);
#pragma unroll
                for (int nt = 0; nt < 4; nt++)
                    mma_f16(acc[mt][nt], al, bh[nt][0], bh[nt][1]);
            }
        }
        __syncthreads();
    }

    // epilogue (unscale weights by 1/64 first)
#pragma unroll
    for (int mt = 0; mt < 4; mt++) {
        const int grow = bm + wm * 64 + mt * 16 + gid;
        const size_t r0o = (size_t)grow * ldc, r1o = (size_t)(grow + 8) * ldc;
#pragma unroll
        for (int nt = 0; nt < 4; nt++) {
            const int gcol = bn + wn * 32 + nt * 8 + tig * 2;
#pragma unroll
            for (int half = 0; half < 2; half++) {
                const int cc = gcol + half;
                if (cc >= N) continue;
                const size_t i0 = r0o + cc, i1 = r1o + cc;
                float v0 = acc[mt][nt][half] * WUNSCALE;
                float v1 = acc[mt][nt][2 + half] * WUNSCALE;
                if (bias) { const float b = bias[cc]; v0 += b; v1 += b; }
                if (gate) {
                    const float gv0 = gate[i0], gv1 = gate[i1];
                    v0 *= gv0 / (1.f + expf(-gv0));
                    v1 *= gv1 / (1.f + expf(-gv1));
                }
                if (resid) { v0 += resid[i0]; v1 += resid[i1]; }
                if (C) { C[i0] = v0; C[i1] = v1; }
                if (Chi) {
                    uint16_t h, l;
                    split2h(v0, h, l); Chi[i0] = h; Clo[i0] = l;
                    split2h(v1, h, l); Chi[i1] = h; Clo[i1] = l;
                }
            }
        }
    }
}

// ---------------- RMSNorm (split output) ----------------
__global__ __launch_bounds__(128) void rms_k(
    const float* __restrict__ h, const float* __restrict__ w,
    uint16_t* __restrict__ ohi, uint16_t* __restrict__ olo)
{
    int m = blockIdx.x, t = threadIdx.x;
    const float4* hr = (const float4*)(h + (size_t)m * 512);
    float4 v = hr[t];
    float ss = v.x * v.x + v.y * v.y + v.z * v.z + v.w * v.w;
#pragma unroll
    for (int off = 16; off; off >>= 1) ss += __shfl_down_sync(0xffffffffu, ss, off);
    __shared__ float red[4];
    __shared__ float sc_s;
    if ((t & 31) == 0) red[t >> 5] = ss;
    __syncthreads();
    if (t == 0) sc_s = rsqrtf((red[0] + red[1] + red[2] + red[3]) / 512.f + 1.1920929e-07f);
    __syncthreads();
    float sc = sc_s;
    float4 wv = ((const float4*)w)[t];
    float r0 = v.x * sc * wv.x, r1 = v.y * sc * wv.y, r2 = v.z * sc * wv.z, r3 = v.w * sc * wv.w;
    ushort4 hh, ll;
    split2h(r0, hh.x, ll.x); split2h(r1, hh.y, ll.y);
    split2h(r2, hh.z, ll.z); split2h(r3, hh.w, ll.w);
    ((ushort4*)(ohi + (size_t)m * 512))[t] = hh;
    ((ushort4*)(olo + (size_t)m * 512))[t] = ll;
}

// ---------------- LayerNorm + SiLU (in place, float) ----------------
__global__ __launch_bounds__(128) void lnsilu_k(
    float* __restrict__ h, const float* __restrict__ w, const float* __restrict__ b)
{
    int m = blockIdx.x, t = threadIdx.x;
    float4* hr = (float4*)(h + (size_t)m * 512);
    float4 v = hr[t];
    float s1 = v.x + v.y + v.z + v.w;
    float s2 = v.x * v.x + v.y * v.y + v.z * v.z + v.w * v.w;
#pragma unroll
    for (int off = 16; off; off >>= 1) {
        s1 += __shfl_down_sync(0xffffffffu, s1, off);
        s2 += __shfl_down_sync(0xffffffffu, s2, off);
    }
    __shared__ float red[8];
    __shared__ float st[2];
    if ((t & 31) == 0) { red[t >> 5] = s1; red[4 + (t >> 5)] = s2; }
    __syncthreads();
    if (t == 0) {
        float a = red[0] + red[1] + red[2] + red[3];
        float q = red[4] + red[5] + red[6] + red[7];
        float mean = a / 512.f;
        float var = q / 512.f - mean * mean;
        st[0] = mean; st[1] = rsqrtf(var + 1e-5f);
    }
    __syncthreads();
    float mean = st[0], rstd = st[1];
    float4 wv = ((const float4*)w)[t], bv = ((const float4*)b)[t];
    float x0 = (v.x - mean) * rstd * wv.x + bv.x;
    float x1 = (v.y - mean) * rstd * wv.y + bv.y;
    float x2 = (v.z - mean) * rstd * wv.z + bv.z;
    float x3 = (v.w - mean) * rstd * wv.w + bv.w;
    float4 r;
    r.x = x0 / (1.f + expf(-x0)); r.y = x1 / (1.f + expf(-x1));
    r.z = x2 / (1.f + expf(-x2)); r.w = x3 / (1.f + expf(-x3));
    hr[t] = r;
}

// ---------------- sliding-window attention (rope tables + trimmed loop + online softmax) ----------------
__global__ __launch_bounds__(256) void attn_k(const float* __restrict__ qkv,
                                              const float* __restrict__ rc,
                                              const float* __restrict__ rs,
                                              uint16_t* __restrict__ ohi,
                                              uint16_t* __restrict__ olo)
{
    extern __shared__ float sm[];
    float* Ks = sm;            // 256 x 64
    float* Vs = sm + 16384;    // 256 x 64
    const int n = blockIdx.x, hh = blockIdx.y, b = blockIdx.z;
    const int tid = threadIdx.x;

    {
        int d2 = tid & 31, j0 = tid >> 5;
        for (int j = j0; j < 256; j += 8) {
            int p = (n - 1) * 128 + j;
            if (p >= 0) {
                size_t base = ((size_t)(b * LSEQ + p)) * 1536 + hh * 192 + d2 * 6;
                float k0 = qkv[base + 1], k1 = qkv[base + 4];
                float v0 = qkv[base + 2], v1 = qkv[base + 5];
                float cs = rc[p * 32 + d2], sn = rs[p * 32 + d2];
                Ks[j * 64 + 2 * d2]     = k0 * cs - k1 * sn;
                Ks[j * 64 + 2 * d2 + 1] = k0 * sn + k1 * cs;
                Vs[j * 64 + 2 * d2]     = v0;
                Vs[j * 64 + 2 * d2 + 1] = v1;
            } else {
                Ks[j * 64 + 2 * d2] = 0.f; Ks[j * 64 + 2 * d2 + 1] = 0.f;
                Vs[j * 64 + 2 * d2] = 0.f; Vs[j * 64 + 2 * d2 + 1] = 0.f;
            }
        }
    }
    const int qi = tid >> 1, half = tid & 1;
    const int pq = n * 128 + qi;
    float q[32];
    {
        size_t base = ((size_t)(b * LSEQ + pq)) * 1536 + hh * 192;
#pragma unroll
        for (int t = 0; t < 16; t++) {
            int d2 = half * 16 + t;
            float q0 = qkv[base + d2 * 6], q1 = qkv[base + d2 * 6 + 3];
            float cs = rc[pq * 32 + d2], sn = rs[pq * 32 + d2];
            q[2 * t]     = q0 * cs - q1 * sn;
            q[2 * t + 1] = q0 * sn + q1 * cs;
        }
    }
    __syncthreads();

    const int jstart = (n == 0) ? 128 : qi;
    const int jend = qi + 128;
    // warp-uniform loop bounds: warp covers qi in [16w, 16w+15]
    const int wqi = (tid >> 5) * 16;
    const int jlo = (n == 0) ? 128 : wqi;
    const int jhi = wqi + 15 + 128;    // inclusive

    // single pass, online softmax
    float mx = -1e30f, l = 0.f;
    float o[32];
#pragma unroll
    for (int t = 0; t < 32; t++) o[t] = 0.f;
    for (int j = jlo; j <= jhi; j++) {
        const float4* kr = (const float4*)(Ks + j * 64 + half * 32);
        float s = 0.f;
#pragma unroll
        for (int t = 0; t < 8; t++) {
            float4 kv = kr[t];
            s = fmaf(q[4 * t], kv.x, s); s = fmaf(q[4 * t + 1], kv.y, s);
            s = fmaf(q[4 * t + 2], kv.z, s); s = fmaf(q[4 * t + 3], kv.w, s);
        }
        s += __shfl_xor_sync(0xffffffffu, s, 1);
        if (j >= jstart && j <= jend) {
            if (s > mx) {
                float corr = __expf((mx - s) * 0.125f);
                l *= corr;
#pragma unroll
                for (int t = 0; t < 32; t++) o[t] *= corr;
                mx = s;
            }
            float p = __expf((s - mx) * 0.125f);
            l += p;
            const float4* vr = (const float4*)(Vs + j * 64 + half * 32);
#pragma unroll
            for (int t = 0; t < 8; t++) {
                float4 vv = vr[t];
                o[4 * t]     = fmaf(p, vv.x, o[4 * t]);
                o[4 * t + 1] = fmaf(p, vv.y, o[4 * t + 1]);
                o[4 * t + 2] = fmaf(p, vv.z, o[4 * t + 2]);
                o[4 * t + 3] = fmaf(p, vv.w, o[4 * t + 3]);
            }
        }
    }
    float invl = 1.f / l;
    size_t obase = ((size_t)(b * LSEQ + pq)) * 512 + hh * 64 + half * 32;
#pragma unroll
    for (int t = 0; t < 8; t++) {
        ushort4 hh4, ll4;
        split2h(o[4 * t] * invl,     hh4.x, ll4.x);
        split2h(o[4 * t + 1] * invl, hh4.y, ll4.y);
        split2h(o[4 * t + 2] * invl, hh4.z, ll4.z);
        split2h(o[4 * t + 3] * invl, hh4.w, ll4.w);
        ((ushort4*)(ohi + obase))[t] = hh4;
        ((ushort4*)(olo + obase))[t] = ll4;
    }
}

// ---------------- head: LN+SiLU, 31-dim projection, postprocess ----------------
__device__ __forceinline__ float softplus_f(float x) { return x > 20.f ? x : log1pf(expf(x)); }

__global__ __launch_bounds__(256) void head_k(
    const float* __restrict__ h,
    const float* __restrict__ lw, const float* __restrict__ lb,
    const float* __restrict__ hw, const float* __restrict__ hb,
    float* __restrict__ out)
{
    int m = blockIdx.x, t = threadIdx.x;
    __shared__ float xs[512];
    __shared__ float red[16];
    __shared__ float ysh[31];
    __shared__ float st[2];
    const float* hr = h + (size_t)m * 512;
    float a = hr[t], b2 = hr[t + 256];
    float s1 = a + b2, s2 = a * a + b2 * b2;
#pragma unroll
    for (int off = 16; off; off >>= 1) {
        s1 += __shfl_down_sync(0xffffffffu, s1, off);
        s2 += __shfl_down_sync(0xffffffffu, s2, off);
    }
    if ((t & 31) == 0) { red[t >> 5] = s1; red[8 + (t >> 5)] = s2; }
    __syncthreads();
    if (t == 0) {
        float ss1 = 0.f, ss2 = 0.f;
        for (int i = 0; i < 8; i++) { ss1 += red[i]; ss2 += red[8 + i]; }
        float mean = ss1 / 512.f;
        float var = ss2 / 512.f - mean * mean;
        st[0] = mean; st[1] = rsqrtf(var + 1e-5f);
    }
    __syncthreads();
    float mean = st[0], rstd = st[1];
    float va = (a - mean) * rstd * lw[t] + lb[t];
    float vb = (b2 - mean) * rstd * lw[t + 256] + lb[t + 256];
    xs[t] = va / (1.f + expf(-va));
    xs[t + 256] = vb / (1.f + expf(-vb));
    __syncthreads();
    {
        int nn = t >> 3, p = t & 7;
        bool valid = nn < 31;
        const float* wr = hw + (size_t)(valid ? nn : 0) * 512;
        float acc = 0.f;
#pragma unroll 8
        for (int kk = 0; kk < 64; kk++) {
            int k = kk * 8 + p;
            acc = fmaf(xs[k], wr[k], acc);
        }
        acc += __shfl_down_sync(0xffffffffu, acc, 4, 8);
        acc += __shfl_down_sync(0xffffffffu, acc, 2, 8);
        acc += __shfl_down_sync(0xffffffffu, acc, 1, 8);
        if (valid && p == 0) ysh[nn] = acc + hb[nn];
    }
    __syncthreads();
    if (t == 0) {
        float y[31];
#pragma unroll
        for (int i = 0; i < 31; i++) y[i] = ysh[i];
        float* op = out + (size_t)m * 40;
        int am = 0;
        for (int i = 1; i < 11; i++) if (y[i] > y[am]) am = i;
        float fc_reg = softplus_f(y[11]);
        float fetch = (am < 10) ? (float)(am + 1) : fc_reg;
        int ae = 0;
        for (int i = 1; i < 11; i++) if (y[12 + i] > y[12 + ae]) ae = i;
        float ec_reg = softplus_f(y[23]);
        float execc = (ae < 10) ? (float)(ae + 1) : ec_reg;
        float bm_log = y[24];
        float bm = 1.f / (1.f + expf(-bm_log));
        float icm = fmaxf(y[25], fmaxf(y[26], y[27]));
        float e0 = expf(y[25] - icm), e1 = expf(y[26] - icm), e2 = expf(y[27] - icm);
        float is = e0 + e1 + e2;
        float dcm = fmaxf(y[28], fmaxf(y[29], y[30]));
        float d0 = expf(y[28] - dcm), d1 = expf(y[29] - dcm), d2 = expf(y[30] - dcm);
        float ds = d0 + d1 + d2;
        op[0] = fetch;
        for (int i = 0; i < 11; i++) op[1 + i] = y[i];
        op[12] = fc_reg;
        op[13] = execc;
        for (int i = 0; i < 11; i++) op[14 + i] = y[12 + i];
        op[25] = ec_reg;
        op[26] = bm;
        op[27] = e0 / is; op[28] = e1 / is; op[29] = e2 / is;
        op[30] = d0 / ds; op[31] = d1 / ds; op[32] = d2 / ds;
        op[33] = bm_log;
        op[34] = y[25]; op[35] = y[26]; op[36] = y[27];
        op[37] = y[28]; op[38] = y[29]; op[39] = y[30];
    }
}

// ---------------- launch ----------------
extern "C" void kernel_launch(void* const* d_in, const int* in_sizes, int n_in,
                              void* d_out, int out_size)
{
    const void*  x       = d_in[0];
    const float* emb     = (const float*)d_in[1];
    const float* reg_w   = (const float*)d_in[2];
    const float* reg_b   = (const float*)d_in[3];
    const float* br_w    = (const float*)d_in[4];
    const float* br_b    = (const float*)d_in[5];
    const float* sh_w    = (const float*)d_in[6];
    const float* sh_b    = (const float*)d_in[7];
    const float* inst_w  = (const float*)d_in[8];
    const float* inst_b  = (const float*)d_in[9];
    const float* enc_ln_w = (const float*)d_in[10];
    const float* enc_ln_b = (const float*)d_in[11];
    const float* qkv_w   = (const float*)d_in[12];
    const float* out_w   = (const float*)d_in[13];
    const float* out_b   = (const float*)d_in[14];
    const float* w1_w    = (const float*)d_in[15];
    const float* w1_b    = (const float*)d_in[16];
    const float* w3_w    = (const float*)d_in[17];
    const float* w3_b    = (const float*)d_in[18];
    const float* w2_w    = (const float*)d_in[19];
    const float* w2_b    = (const float*)d_in[20];
    const float* n1_w    = (const float*)d_in[21];
    const float* n2_w    = (const float*)d_in[22];
    const float* head_ln_w = (const float*)d_in[23];
    const float* head_ln_b = (const float*)d_in[24];
    const float* head_w  = (const float*)d_in[25];
    const float* head_b  = (const float*)d_in[26];
    float* out = (float*)d_out;

    void *p;
    cudaGetSymbolAddress(&p, g_cat_hi);  uint16_t* cat_hi = (uint16_t*)p;
    cudaGetSymbolAddress(&p, g_cat_lo);  uint16_t* cat_lo = (uint16_t*)p;
    cudaGetSymbolAddress(&p, g_h);       float* h = (float*)p;
    cudaGetSymbolAddress(&p, g_xn_hi);   uint16_t* xn_hi = (uint16_t*)p;
    cudaGetSymbolAddress(&p, g_xn_lo);   uint16_t* xn_lo = (uint16_t*)p;
    cudaGetSymbolAddress(&p, g_qkv);     float* qkv = (float*)p;
    cudaGetSymbolAddress(&p, g_att_hi);  uint16_t* att_hi = (uint16_t*)p;
    cudaGetSymbolAddress(&p, g_att_lo);  uint16_t* att_lo = (uint16_t*)p;
    cudaGetSymbolAddress(&p, g_uf);      float* uf = (float*)p;
    cudaGetSymbolAddress(&p, g_u_hi);    uint16_t* u_hi = (uint16_t*)p;
    cudaGetSymbolAddress(&p, g_u_lo);    uint16_t* u_lo = (uint16_t*)p;
    cudaGetSymbolAddress(&p, g_w2p);     float* w2p = (float*)p;
    cudaGetSymbolAddress(&p, g_whi);     uint16_t* whi = (uint16_t*)p;
    cudaGetSymbolAddress(&p, g_wlo);     uint16_t* wlo = (uint16_t*)p;
    cudaGetSymbolAddress(&p, g_ropec);   float* ropec = (float*)p;
    cudaGetSymbolAddress(&p, g_ropes);   float* ropes = (float*)p;

    cudaFuncSetAttribute(attn_k, cudaFuncAttributeMaxDynamicSharedMemorySize, 131072);
    cudaFuncSetAttribute(tgemm_k, cudaFuncAttributeMaxDynamicSharedMemorySize, TG_DSMEM);

    detect_k<<<1, 1>>>((const int*)x);
    embed_k<<<NTOK, 192>>>(x, emb, reg_w, reg_b, br_w, br_b, sh_w, sh_b, cat_hi, cat_lo);
    padw2_k<<<1536, 256>>>(w2_w, w2p);
    ropetab_k<<<LSEQ, 32>>>(ropec, ropes);

    splitw_k<<<1024, 256>>>(inst_w, whi + OFF_INST, wlo + OFF_INST, CNT_INST);
    splitw_k<<<2048, 256>>>(qkv_w,  whi + OFF_QKV,  wlo + OFF_QKV,  CNT_QKV);
    splitw_k<<<1024, 256>>>(out_w,  whi + OFF_OUT,  wlo + OFF_OUT,  CNT_OUT);
    splitw_k<<<2048, 256>>>(w1_w,   whi + OFF_W1,   wlo + OFF_W1,   CNT_W1);
    splitw_k<<<2048, 256>>>(w3_w,   whi + OFF_W3,   wlo + OFF_W3,   CNT_W3);
    splitw_k<<<2048, 256>>>(w2p,    whi + OFF_W2,   wlo + OFF_W2,   CNT_W2);

    // encoder: h = silu(cat) @ inst_w.T + inst_b
    tgemm_k<<<dim3(4, 64), 256, TG_DSMEM>>>(cat_hi, cat_lo, 768,
                                            whi + OFF_INST, wlo + OFF_INST, 768,
                                            inst_b, nullptr, nullptr,
                                            h, nullptr, nullptr, 512, 512, 768);
    lnsilu_k<<<NTOK, 128>>>(h, enc_ln_w, enc_ln_b);

    for (int l = 0; l < 3; l++) {
        rms_k<<<NTOK, 128>>>(h, n1_w + l * 512, xn_hi, xn_lo);
        tgemm_k<<<dim3(12, 64), 256, TG_DSMEM>>>(xn_hi, xn_lo, 512,
                                                 whi + OFF_QKV + (size_t)l * 1536 * 512,
                                                 wlo + OFF_QKV + (size_t)l * 1536 * 512, 512,
                                                 nullptr, nullptr, nullptr,
                                                 qkv, nullptr, nullptr, 1536, 1536, 512);
        attn_k<<<dim3(16, 8, 4), 256, 131072>>>(qkv, ropec, ropes, att_hi, att_lo);
        tgemm_k<<<dim3(4, 64), 256, TG_DSMEM>>>(att_hi, att_lo, 512,
                                                whi + OFF_OUT + (size_t)l * 512 * 512,
                                                wlo + OFF_OUT + (size_t)l * 512 * 512, 512,
                                                out_b + l * 512, h, nullptr,
                                                h, nullptr, nullptr, 512, 512, 512);
        rms_k<<<NTOK, 128>>>(h, n2_w + l * 512, xn_hi, xn_lo);
        tgemm_k<<<dim3(11, 64), 256, TG_DSMEM>>>(xn_hi, xn_lo, 512,
                                                 whi + OFF_W1 + (size_t)l * DFF * 512,
                                                 wlo + OFF_W1 + (size_t)l * DFF * 512, 512,
                                                 w1_b + l * DFF, nullptr, nullptr,
                                                 uf, nullptr, nullptr, DFFP, DFF, 512);
        tgemm_k<<<dim3(11, 64), 256, TG_DSMEM>>>(xn_hi, xn_lo, 512,
                                                 whi + OFF_W3 + (size_t)l * DFF * 512,
                                                 wlo + OFF_W3 + (size_t)l * DFF * 512, 512,
                                                 w3_b + l * DFF, nullptr, uf,
                                                 nullptr, u_hi, u_lo, DFFP, DFF, 512);
        tgemm_k<<<dim3(4, 64), 256, TG_DSMEM>>>(u_hi, u_lo, DFFP,
                                                whi + OFF_W2 + (size_t)l * 512 * DFFP,
                                                wlo + OFF_W2 + (size_t)l * 512 * DFFP, DFFP,
                                                w2_b + l * 512, h, nullptr,
                                                h, nullptr, nullptr, 512, 512, 1376);
    }

    head_k<<<NTOK, 256>>>(h, head_ln_w, head_ln_b, head_w, head_b, out);
}

// round 17
// speedup vs baseline: 1.3220x; 1.0207x over previous
#include <cuda_runtime.h>
#include <cuda_fp16.h>
#include <cstdint>
#include <cstddef>

#define NTOK 8192
#define LSEQ 2048
#define DMODEL 512
#define DFF 1365
#define DFFP 1376

// weight-plane offsets (fp16 elements)
#define OFF_INST 0
#define CNT_INST (512 * 768)
#define OFF_QKV  (OFF_INST + CNT_INST)
#define CNT_QKV  (3 * 1536 * 512)
#define OFF_OUT  (OFF_QKV + CNT_QKV)
#define CNT_OUT  (3 * 512 * 512)
#define OFF_W1   (OFF_OUT + CNT_OUT)
#define CNT_W1   (3 * DFF * 512)
#define OFF_W3   (OFF_W1 + CNT_W1)
#define CNT_W3   (3 * DFF * 512)
#define OFF_W2   (OFF_W3 + CNT_W3)
#define CNT_W2   (3 * 512 * DFFP)
#define WTOT     (OFF_W2 + CNT_W2)

#define WSCALE   64.0f
#define WUNSCALE 0.015625f

// ---------------- scratch (device globals; allocation-free) ----------------
__device__ __align__(16) uint16_t g_cat_hi[NTOK * 768];
__device__ __align__(16) uint16_t g_cat_lo[NTOK * 768];
__device__ __align__(16) float    g_h[NTOK * 512];
__device__ __align__(16) uint16_t g_xn_hi[NTOK * 512];
__device__ __align__(16) uint16_t g_xn_lo[NTOK * 512];
__device__ __align__(16) float    g_qkv[NTOK * 1536];
__device__ __align__(16) uint16_t g_att_hi[NTOK * 512];
__device__ __align__(16) uint16_t g_att_lo[NTOK * 512];
__device__ __align__(16) float    g_uf[NTOK * DFFP];      // w1 output (pads never read)
__device__ __align__(16) uint16_t g_u_hi[NTOK * DFFP];    // pads stay 0 (static zero init)
__device__ __align__(16) uint16_t g_u_lo[NTOK * DFFP];
__device__ __align__(16) float    g_w2p[3 * 512 * DFFP];
__device__ __align__(16) uint16_t g_whi[WTOT];
__device__ __align__(16) uint16_t g_wlo[WTOT];
__device__ __align__(16) float    g_ropec[LSEQ * 32];
__device__ __align__(16) float    g_ropes[LSEQ * 32];
__device__ int g_is64;

// ---------------- helpers ----------------
__device__ __forceinline__ uint32_t smem_u32(const void* p) {
    uint32_t a;
    asm("{ .reg .u64 t; cvta.to.shared.u64 t, %1; cvt.u32.u64 %0, t; }" : "=r"(a) : "l"(p));
    return a;
}
__device__ __forceinline__ void split2h(float x, uint16_t& h, uint16_t& l) {
    __half hh = __float2half_rn(x);
    __half ll = __float2half_rn(x - __half2float(hh));
    h = __half_as_ushort(hh);
    l = __half_as_ushort(ll);
}
__device__ __forceinline__ void mma_f16(float* d, const uint32_t* a, uint32_t b0, uint32_t b1) {
    asm volatile(
        "mma.sync.aligned.m16n8k16.row.col.f32.f16.f16.f32 "
        "{%0,%1,%2,%3}, {%4,%5,%6,%7}, {%8,%9}, {%0,%1,%2,%3};"
        : "+f"(d[0]), "+f"(d[1]), "+f"(d[2]), "+f"(d[3])
        : "r"(a[0]), "r"(a[1]), "r"(a[2]), "r"(a[3]), "r"(b0), "r"(b1));
}
__device__ __forceinline__ void cpasync16(uint32_t dst, const void* src) {
    asm volatile("cp.async.cg.shared.global [%0], [%1], 16;" :: "r"(dst), "l"(src) : "memory");
}

// ---------------- dtype probe for x (int64 vs int32) ----------------
__global__ void detect_k(const int* x) {
    long long s = 0;
    for (int i = 1; i < 8192; i += 2) { int v = x[i]; s += (v < 0) ? -(long long)v : (long long)v; }
    g_is64 = (s == 0) ? 1 : 0;
}

// ---------------- rope tables (bitwise-identical to in-kernel sincosf) ----------------
__global__ void ropetab_k(float* rc, float* rs) {
    int p = blockIdx.x, d2 = threadIdx.x;
    float inv = expf((float)d2 * -0.28782313662425572f);
    float sn, cs;
    sincosf((float)p * inv, &sn, &cs);
    rc[p * 32 + d2] = cs;
    rs[p * 32 + d2] = sn;
}

// ---------------- split weights (scaled by 64) into fp16 hi/lo planes ----------------
__global__ void splitw_k(const float* __restrict__ src, uint16_t* __restrict__ hi,
                         uint16_t* __restrict__ lo, int n)
{
    int stride = gridDim.x * 256;
    for (int i = blockIdx.x * 256 + threadIdx.x; i < n; i += stride) {
        uint16_t h, l;
        split2h(src[i] * WSCALE, h, l);
        hi[i] = h; lo[i] = l;
    }
}

// ---------------- split qkv weights with row permutation: new col n=t*512+h*64+dk ----------------
__global__ void splitqkv_k(const float* __restrict__ src, uint16_t* __restrict__ hi,
                           uint16_t* __restrict__ lo)
{
    int stride = gridDim.x * 256;
    for (int i = blockIdx.x * 256 + threadIdx.x; i < CNT_QKV; i += stride) {
        int k = i & 511, row = i >> 9;
        int l = row / 1536, n = row - l * 1536;
        int t = n >> 9, rem = n & 511, hh = rem >> 6, dk = rem & 63;
        int orig = hh * 192 + dk * 3 + t;
        float val = src[((size_t)(l * 1536 + orig)) * 512 + k] * WSCALE;
        uint16_t h, lw;
        split2h(val, h, lw);
        hi[i] = h; lo[i] = lw;
    }
}

// ---------------- pad w2 (3,512,1365) -> (3,512,1376) ----------------
__global__ void padw2_k(const float* __restrict__ w2, float* __restrict__ o)
{
    int row = blockIdx.x;  // 0..1535
    const float* src = w2 + (size_t)row * DFF;
    float* dst = o + (size_t)row * DFFP;
    for (int k = threadIdx.x; k < DFFP; k += 256) dst[k] = (k < DFF) ? src[k] : 0.f;
}

// ---------------- embed + input projections + silu (split output) ----------------
__global__ __launch_bounds__(192) void embed_k(
    const void* __restrict__ xraw,
    const float* __restrict__ emb,
    const float* __restrict__ reg_w, const float* __restrict__ reg_b,
    const float* __restrict__ br_w,  const float* __restrict__ br_b,
    const float* __restrict__ sh_w,  const float* __restrict__ sh_b,
    uint16_t* __restrict__ chi, uint16_t* __restrict__ clo)
{
    int m = blockIdx.x;
    int t = threadIdx.x;
    __shared__ float vals[288];
    __shared__ int tok_s;
    if (g_is64) {
        const long long* xr = (const long long*)xraw + (size_t)m * 289;
        if (t == 0) tok_s = (int)xr[0];
        for (int i = t; i < 288; i += 192) vals[i] = (float)xr[1 + i];
    } else {
        const int* xr = (const int*)xraw + (size_t)m * 289;
        if (t == 0) tok_s = xr[0];
        for (int i = t; i < 288; i += 192) vals[i] = (float)xr[1 + i];
    }
    __syncthreads();
    int tok = tok_s;
    float c0 = emb[(size_t)tok * 192 + t];
    float c1 = reg_b[t];
    const float* rw = reg_w + (size_t)t * 64;
#pragma unroll 8
    for (int k = 0; k < 64; k++) c1 = fmaf(vals[k], rw[k], c1);
    float c2 = br_b[t];
    const float* bw = br_w + (size_t)t * 32;
#pragma unroll 8
    for (int k = 0; k < 32; k++) c2 = fmaf(vals[256 + k], bw[k], c2);
    float c3 = sh_b[t];
    const float* sw = sh_w + (size_t)t * 192;
#pragma unroll 8
    for (int k = 0; k < 192; k++) c3 = fmaf(vals[64 + k], sw[k], c3);
    float s0 = c0 / (1.f + expf(-c0));
    float s1 = c1 / (1.f + expf(-c1));
    float s2 = c2 / (1.f + expf(-c2));
    float s3 = c3 / (1.f + expf(-c3));
    size_t base = (size_t)m * 768;
    uint16_t h, l;
    split2h(s0, h, l); chi[base + t] = h;        clo[base + t] = l;
    split2h(s1, h, l); chi[base + 192 + t] = h;  clo[base + 192 + t] = l;
    split2h(s2, h, l); chi[base + 384 + t] = h;  clo[base + 384 + t] = l;
    split2h(s3, h, l); chi[base + 576 + t] = h;  clo[base + 576 + t] = l;
}

// ---------------- 3xFP16 GEMM: pre-split fp16 hi/lo planes, cp.async, scalar frags ----------------
#define TSTRIDE 40
#define PS (128 * TSTRIDE)
#define TG_DSMEM (2 * 4 * PS * 2)

__global__ __launch_bounds__(256, 2) void tgemm_k(
    const uint16_t* __restrict__ Ahg, const uint16_t* __restrict__ Alg, int lda,
    const uint16_t* __restrict__ Whg, const uint16_t* __restrict__ Wlg, int ldw,
    const float* __restrict__ bias, const float* __restrict__ resid,
    const float* __restrict__ gate,
    float* __restrict__ C, uint16_t* __restrict__ Chi, uint16_t* __restrict__ Clo,
    int ldc, int N, int K)
{
    extern __shared__ uint16_t dsm[];
    const uint32_t sb = smem_u32(dsm);

    const int tid = threadIdx.x;
    const int wid = tid >> 5, lane = tid & 31;
    const int wm = wid >> 2, wn = wid & 3;
    const int gid = lane >> 2, tig = lane & 3;

    const int bm = blockIdx.y * 128, bn = blockIdx.x * 128;

    const int lrow = tid >> 1, lsub = (tid & 1) * 16;
    const uint16_t* Agh = Ahg + (size_t)(bm + lrow) * lda;
    const uint16_t* Agl = Alg + (size_t)(bm + lrow) * lda;
    const int wrow = bn + lrow;
    const int wsafe = (wrow < N) ? wrow : 0;
    const uint16_t* Wgh = Whg + (size_t)wsafe * ldw;
    const uint16_t* Wgl = Wlg + (size_t)wsafe * ldw;

    const uint32_t dbase = sb + 2 * (uint32_t)(lrow * TSTRIDE + lsub);

    float acc[4][4][4];
#pragma unroll
    for (int i = 0; i < 4; i++)
#pragma unroll
        for (int j = 0; j < 4; j++)
#pragma unroll
            for (int e = 0; e < 4; e++) acc[i][j][e] = 0.f;

    const int NC = K >> 5;

#define ISSUE(c, buf)                                                        \
    do {                                                                     \
        const int ke = (c) * 32 + lsub;                                      \
        uint32_t d = dbase + (uint32_t)(buf) * (4 * PS * 2);                 \
        cpasync16(d, Agh + ke);               cpasync16(d + 16, Agh + ke + 8);\
        cpasync16(d + PS * 2, Agl + ke);      cpasync16(d + PS * 2 + 16, Agl + ke + 8);\
        cpasync16(d + 2 * PS * 2, Wgh + ke);  cpasync16(d + 2 * PS * 2 + 16, Wgh + ke + 8);\
        cpasync16(d + 3 * PS * 2, Wgl + ke);  cpasync16(d + 3 * PS * 2 + 16, Wgl + ke + 8);\
        asm volatile("cp.async.commit_group;" ::: "memory");                 \
    } while (0)

    ISSUE(0, 0);

    for (int c = 0; c < NC; c++) {
        const int buf = c & 1;
        if (c + 1 < NC) {
            ISSUE(c + 1, (c + 1) & 1);
            asm volatile("cp.async.wait_group 1;" ::: "memory");
        } else {
            asm volatile("cp.async.wait_group 0;" ::: "memory");
        }
        __syncthreads();

        const uint16_t* Ah = dsm + buf * 4 * PS;
        const uint16_t* Al = Ah + PS;
        const uint16_t* Bh = Ah + 2 * PS;
        const uint16_t* Bl = Ah + 3 * PS;
#pragma unroll
        for (int s = 0; s < 2; s++) {
            const int kk = s * 16 + 2 * tig;
            uint32_t bh[4][2], bl[4][2];
#pragma unroll
            for (int nt = 0; nt < 4; nt++) {
                const int n0 = (wn * 32 + nt * 8 + gid) * TSTRIDE + kk;
                bh[nt][0] = *(const uint32_t*)(Bh + n0);
                bh[nt][1] = *(const uint32_t*)(Bh + n0 + 8);
                bl[nt][0] = *(const uint32_t*)(Bl + n0);
                bl[nt][1] = *(const uint32_t*)(Bl + n0 + 8);
            }
#pragma unroll
            for (int mt = 0; mt < 4; mt++) {
                const int r0 = (wm * 64 + mt * 16 + gid) * TSTRIDE + kk;
                const int r1 = r0 + 8 * TSTRIDE;
                uint32_t ah[4], al[4];
                ah[0] = *(const uint32_t*)(Ah + r0); ah[1] = *(const uint32_t*)(Ah + r1);
                ah[2] = *(const uint32_t*)(Ah + r0 + 8); ah[3] = *(const uint32_t*)(Ah + r1 + 8);
                al[0] = *(const uint32_t*)(Al + r0); al[1] = *(const uint32_t*)(Al + r1);
                al[2] = *(const uint32_t*)(Al + r0 + 8); al[3] = *(const uint32_t*)(Al + r1 + 8);
#pragma unroll
                for (int nt = 0; nt < 4; nt++)
                    mma_f16(acc[mt][nt], ah, bh[nt][0], bh[nt][1]);
#pragma unroll
                for (int nt = 0; nt < 4; nt++)
                    mma_f16(acc[mt][nt], ah, bl[nt][0], bl[nt][1]);
#pragma unroll
                for (int nt = 0; nt < 4; nt++)
                    mma_f16(acc[mt][nt], al, bh[nt][0], bh[nt][1]);
            }
        }
        __syncthreads();
    }

    // epilogue (unscale weights by 1/64 first)
#pragma unroll
    for (int mt = 0; mt < 4; mt++) {
        const int grow = bm + wm * 64 + mt * 16 + gid;
        const size_t r0o = (size_t)grow * ldc, r1o = (size_t)(grow + 8) * ldc;
#pragma unroll
        for (int nt = 0; nt < 4; nt++) {
            const int gcol = bn + wn * 32 + nt * 8 + tig * 2;
#pragma unroll
            for (int half = 0; half < 2; half++) {
                const int cc = gcol + half;
                if (cc >= N) continue;
                const size_t i0 = r0o + cc, i1 = r1o + cc;
                float v0 = acc[mt][nt][half] * WUNSCALE;
                float v1 = acc[mt][nt][2 + half] * WUNSCALE;
                if (bias) { const float b = bias[cc]; v0 += b; v1 += b; }
                if (gate) {
                    const float gv0 = gate[i0], gv1 = gate[i1];
                    v0 *= gv0 / (1.f + expf(-gv0));
                    v1 *= gv1 / (1.f + expf(-gv1));
                }
                if (resid) { v0 += resid[i0]; v1 += resid[i1]; }
                if (C) { C[i0] = v0; C[i1] = v1; }
                if (Chi) {
                    uint16_t h, l;
                    split2h(v0, h, l); Chi[i0] = h; Clo[i0] = l;
                    split2h(v1, h, l); Chi[i1] = h; Clo[i1] = l;
                }
            }
        }
    }
}

// ---------------- RMSNorm (split output) ----------------
__global__ __launch_bounds__(128) void rms_k(
    const float* __restrict__ h, const float* __restrict__ w,
    uint16_t* __restrict__ ohi, uint16_t* __restrict__ olo)
{
    int m = blockIdx.x, t = threadIdx.x;
    const float4* hr = (const float4*)(h + (size_t)m * 512);
    float4 v = hr[t];
    float ss = v.x * v.x + v.y * v.y + v.z * v.z + v.w * v.w;
#pragma unroll
    for (int off = 16; off; off >>= 1) ss += __shfl_down_sync(0xffffffffu, ss, off);
    __shared__ float red[4];
    __shared__ float sc_s;
    if ((t & 31) == 0) red[t >> 5] = ss;
    __syncthreads();
    if (t == 0) sc_s = rsqrtf((red[0] + red[1] + red[2] + red[3]) / 512.f + 1.1920929e-07f);
    __syncthreads();
    float sc = sc_s;
    float4 wv = ((const float4*)w)[t];
    float r0 = v.x * sc * wv.x, r1 = v.y * sc * wv.y, r2 = v.z * sc * wv.z, r3 = v.w * sc * wv.w;
    ushort4 hh, ll;
    split2h(r0, hh.x, ll.x); split2h(r1, hh.y, ll.y);
    split2h(r2, hh.z, ll.z); split2h(r3, hh.w, ll.w);
    ((ushort4*)(ohi + (size_t)m * 512))[t] = hh;
    ((ushort4*)(olo + (size_t)m * 512))[t] = ll;
}

// ---------------- LayerNorm + SiLU (in place, float) ----------------
__global__ __launch_bounds__(128) void lnsilu_k(
    float* __restrict__ h, const float* __restrict__ w, const float* __restrict__ b)
{
    int m = blockIdx.x, t = threadIdx.x;
    float4* hr = (float4*)(h + (size_t)m * 512);
    float4 v = hr[t];
    float s1 = v.x + v.y + v.z + v.w;
    float s2 = v.x * v.x + v.y * v.y + v.z * v.z + v.w * v.w;
#pragma unroll
    for (int off = 16; off; off >>= 1) {
        s1 += __shfl_down_sync(0xffffffffu, s1, off);
        s2 += __shfl_down_sync(0xffffffffu, s2, off);
    }
    __shared__ float red[8];
    __shared__ float st[2];
    if ((t & 31) == 0) { red[t >> 5] = s1; red[4 + (t >> 5)] = s2; }
    __syncthreads();
    if (t == 0) {
        float a = red[0] + red[1] + red[2] + red[3];
        float q = red[4] + red[5] + red[6] + red[7];
        float mean = a / 512.f;
        float var = q / 512.f - mean * mean;
        st[0] = mean; st[1] = rsqrtf(var + 1e-5f);
    }
    __syncthreads();
    float mean = st[0], rstd = st[1];
    float4 wv = ((const float4*)w)[t], bv = ((const float4*)b)[t];
    float x0 = (v.x - mean) * rstd * wv.x + bv.x;
    float x1 = (v.y - mean) * rstd * wv.y + bv.y;
    float x2 = (v.z - mean) * rstd * wv.z + bv.z;
    float x3 = (v.w - mean) * rstd * wv.w + bv.w;
    float4 r;
    r.x = x0 / (1.f + expf(-x0)); r.y = x1 / (1.f + expf(-x1));
    r.z = x2 / (1.f + expf(-x2)); r.w = x3 / (1.f + expf(-x3));
    hr[t] = r;
}

// ---------------- sliding-window attention: coalesced [t][h][dk] qkv layout ----------------
__global__ __launch_bounds__(256) void attn_k(const float* __restrict__ qkv,
                                              const float* __restrict__ rc,
                                              const float* __restrict__ rs,
                                              uint16_t* __restrict__ ohi,
                                              uint16_t* __restrict__ olo)
{
    extern __shared__ float sm[];
    float* Ks = sm;            // 256 x 64
    float* Vs = sm + 16384;    // 256 x 64
    const int n = blockIdx.x, hh = blockIdx.y, b = blockIdx.z;
    const int tid = threadIdx.x;

    {
        int c4 = tid & 15, j0 = tid >> 4;   // 16 float4 chunks per row, 16 rows per pass
        for (int j = j0; j < 256; j += 16) {
            int p = (n - 1) * 128 + j;
            if (p >= 0) {
                size_t base = ((size_t)(b * LSEQ + p)) * 1536 + hh * 64 + c4 * 4;
                float4 kv4 = *(const float4*)(qkv + base + 512);
                float4 vv4 = *(const float4*)(qkv + base + 1024);
                float cs0 = rc[p * 32 + 2 * c4],     sn0 = rs[p * 32 + 2 * c4];
                float cs1 = rc[p * 32 + 2 * c4 + 1], sn1 = rs[p * 32 + 2 * c4 + 1];
                float4 kr;
                kr.x = kv4.x * cs0 - kv4.y * sn0;
                kr.y = kv4.x * sn0 + kv4.y * cs0;
                kr.z = kv4.z * cs1 - kv4.w * sn1;
                kr.w = kv4.z * sn1 + kv4.w * cs1;
                *(float4*)(Ks + j * 64 + c4 * 4) = kr;
                *(float4*)(Vs + j * 64 + c4 * 4) = vv4;
            } else {
                *(float4*)(Ks + j * 64 + c4 * 4) = make_float4(0.f, 0.f, 0.f, 0.f);
                *(float4*)(Vs + j * 64 + c4 * 4) = make_float4(0.f, 0.f, 0.f, 0.f);
            }
        }
    }
    const int qi = tid >> 1, half = tid & 1;
    const int pq = n * 128 + qi;
    float q[32];
    {
        size_t base = ((size_t)(b * LSEQ + pq)) * 1536 + hh * 64 + half * 32;
#pragma unroll
        for (int t4 = 0; t4 < 8; t4++) {
            float4 qv = *(const float4*)(qkv + base + t4 * 4);
            int pr = half * 16 + 2 * t4;
            float cs0 = rc[pq * 32 + pr],     sn0 = rs[pq * 32 + pr];
            float cs1 = rc[pq * 32 + pr + 1], sn1 = rs[pq * 32 + pr + 1];
            q[4 * t4]     = qv.x * cs0 - qv.y * sn0;
            q[4 * t4 + 1] = qv.x * sn0 + qv.y * cs0;
            q[4 * t4 + 2] = qv.z * cs1 - qv.w * sn1;
            q[4 * t4 + 3] = qv.z * sn1 + qv.w * cs1;
        }
    }
    __syncthreads();

    const int jstart = (n == 0) ? 128 : qi;
    const int jend = qi + 128;
    const int wqi = (tid >> 5) * 16;
    const int jlo = (n == 0) ? 128 : wqi;
    const int jhi = wqi + 15 + 128;    // inclusive

    // single pass, online softmax
    float mx = -1e30f, l = 0.f;
    float o[32];
#pragma unroll
    for (int t = 0; t < 32; t++) o[t] = 0.f;
    for (int j = jlo; j <= jhi; j++) {
        const float4* kr = (const float4*)(Ks + j * 64 + half * 32);
        float s = 0.f;
#pragma unroll
        for (int t = 0; t < 8; t++) {
            float4 kv = kr[t];
            s = fmaf(q[4 * t], kv.x, s); s = fmaf(q[4 * t + 1], kv.y, s);
            s = fmaf(q[4 * t + 2], kv.z, s); s = fmaf(q[4 * t + 3], kv.w, s);
        }
        s += __shfl_xor_sync(0xffffffffu, s, 1);
        if (j >= jstart && j <= jend) {
            if (s > mx) {
                float corr = __expf((mx - s) * 0.125f);
                l *= corr;
#pragma unroll
                for (int t = 0; t < 32; t++) o[t] *= corr;
                mx = s;
            }
            float p = __expf((s - mx) * 0.125f);
            l += p;
            const float4* vr = (const float4*)(Vs + j * 64 + half * 32);
#pragma unroll
            for (int t = 0; t < 8; t++) {
                float4 vv = vr[t];
                o[4 * t]     = fmaf(p, vv.x, o[4 * t]);
                o[4 * t + 1] = fmaf(p, vv.y, o[4 * t + 1]);
                o[4 * t + 2] = fmaf(p, vv.z, o[4 * t + 2]);
                o[4 * t + 3] = fmaf(p, vv.w, o[4 * t + 3]);
            }
        }
    }
    float invl = 1.f / l;
    size_t obase = ((size_t)(b * LSEQ + pq)) * 512 + hh * 64 + half * 32;
#pragma unroll
    for (int t = 0; t < 8; t++) {
        ushort4 hh4, ll4;
        split2h(o[4 * t] * invl,     hh4.x, ll4.x);
        split2h(o[4 * t + 1] * invl, hh4.y, ll4.y);
        split2h(o[4 * t + 2] * invl, hh4.z, ll4.z);
        split2h(o[4 * t + 3] * invl, hh4.w, ll4.w);
        ((ushort4*)(ohi + obase))[t] = hh4;
        ((ushort4*)(olo + obase))[t] = ll4;
    }
}

// ---------------- head: LN+SiLU, 31-dim projection, postprocess ----------------
__device__ __forceinline__ float softplus_f(float x) { return x > 20.f ? x : log1pf(expf(x)); }

__global__ __launch_bounds__(256) void head_k(
    const float* __restrict__ h,
    const float* __restrict__ lw, const float* __restrict__ lb,
    const float* __restrict__ hw, const float* __restrict__ hb,
    float* __restrict__ out)
{
    int m = blockIdx.x, t = threadIdx.x;
    __shared__ float xs[512];
    __shared__ float red[16];
    __shared__ float ysh[31];
    __shared__ float st[2];
    const float* hr = h + (size_t)m * 512;
    float a = hr[t], b2 = hr[t + 256];
    float s1 = a + b2, s2 = a * a + b2 * b2;
#pragma unroll
    for (int off = 16; off; off >>= 1) {
        s1 += __shfl_down_sync(0xffffffffu, s1, off);
        s2 += __shfl_down_sync(0xffffffffu, s2, off);
    }
    if ((t & 31) == 0) { red[t >> 5] = s1; red[8 + (t >> 5)] = s2; }
    __syncthreads();
    if (t == 0) {
        float ss1 = 0.f, ss2 = 0.f;
        for (int i = 0; i < 8; i++) { ss1 += red[i]; ss2 += red[8 + i]; }
        float mean = ss1 / 512.f;
        float var = ss2 / 512.f - mean * mean;
        st[0] = mean; st[1] = rsqrtf(var + 1e-5f);
    }
    __syncthreads();
    float mean = st[0], rstd = st[1];
    float va = (a - mean) * rstd * lw[t] + lb[t];
    float vb = (b2 - mean) * rstd * lw[t + 256] + lb[t + 256];
    xs[t] = va / (1.f + expf(-va));
    xs[t + 256] = vb / (1.f + expf(-vb));
    __syncthreads();
    {
        int nn = t >> 3, p = t & 7;
        bool valid = nn < 31;
        const float* wr = hw + (size_t)(valid ? nn : 0) * 512;
        float acc = 0.f;
#pragma unroll 8
        for (int kk = 0; kk < 64; kk++) {
            int k = kk * 8 + p;
            acc = fmaf(xs[k], wr[k], acc);
        }
        acc += __shfl_down_sync(0xffffffffu, acc, 4, 8);
        acc += __shfl_down_sync(0xffffffffu, acc, 2, 8);
        acc += __shfl_down_sync(0xffffffffu, acc, 1, 8);
        if (valid && p == 0) ysh[nn] = acc + hb[nn];
    }
    __syncthreads();
    if (t == 0) {
        float y[31];
#pragma unroll
        for (int i = 0; i < 31; i++) y[i] = ysh[i];
        float* op = out + (size_t)m * 40;
        int am = 0;
        for (int i = 1; i < 11; i++) if (y[i] > y[am]) am = i;
        float fc_reg = softplus_f(y[11]);
        float fetch = (am < 10) ? (float)(am + 1) : fc_reg;
        int ae = 0;
        for (int i = 1; i < 11; i++) if (y[12 + i] > y[12 + ae]) ae = i;
        float ec_reg = softplus_f(y[23]);
        float execc = (ae < 10) ? (float)(ae + 1) : ec_reg;
        float bm_log = y[24];
        float bm = 1.f / (1.f + expf(-bm_log));
        float icm = fmaxf(y[25], fmaxf(y[26], y[27]));
        float e0 = expf(y[25] - icm), e1 = expf(y[26] - icm), e2 = expf(y[27] - icm);
        float is = e0 + e1 + e2;
        float dcm = fmaxf(y[28], fmaxf(y[29], y[30]));
        float d0 = expf(y[28] - dcm), d1 = expf(y[29] - dcm), d2 = expf(y[30] - dcm);
        float ds = d0 + d1 + d2;
        op[0] = fetch;
        for (int i = 0; i < 11; i++) op[1 + i] = y[i];
        op[12] = fc_reg;
        op[13] = execc;
        for (int i = 0; i < 11; i++) op[14 + i] = y[12 + i];
        op[25] = ec_reg;
        op[26] = bm;
        op[27] = e0 / is; op[28] = e1 / is; op[29] = e2 / is;
        op[30] = d0 / ds; op[31] = d1 / ds; op[32] = d2 / ds;
        op[33] = bm_log;
        op[34] = y[25]; op[35] = y[26]; op[36] = y[27];
        op[37] = y[28]; op[38] = y[29]; op[39] = y[30];
    }
}

// ---------------- launch ----------------
extern "C" void kernel_launch(void* const* d_in, const int* in_sizes, int n_in,
                              void* d_out, int out_size)
{
    const void*  x       = d_in[0];
    const float* emb     = (const float*)d_in[1];
    const float* reg_w   = (const float*)d_in[2];
    const float* reg_b   = (const float*)d_in[3];
    const float* br_w    = (const float*)d_in[4];
    const float* br_b    = (const float*)d_in[5];
    const float* sh_w    = (const float*)d_in[6];
    const float* sh_b    = (const float*)d_in[7];
    const float* inst_w  = (const float*)d_in[8];
    const float* inst_b  = (const float*)d_in[9];
    const float* enc_ln_w = (const float*)d_in[10];
    const float* enc_ln_b = (const float*)d_in[11];
    const float* qkv_w   = (const float*)d_in[12];
    const float* out_w   = (const float*)d_in[13];
    const float* out_b   = (const float*)d_in[14];
    const float* w1_w    = (const float*)d_in[15];
    const float* w1_b    = (const float*)d_in[16];
    const float* w3_w    = (const float*)d_in[17];
    const float* w3_b    = (const float*)d_in[18];
    const float* w2_w    = (const float*)d_in[19];
    const float* w2_b    = (const float*)d_in[20];
    const float* n1_w    = (const float*)d_in[21];
    const float* n2_w    = (const float*)d_in[22];
    const float* head_ln_w = (const float*)d_in[23];
    const float* head_ln_b = (const float*)d_in[24];
    const float* head_w  = (const float*)d_in[25];
    const float* head_b  = (const float*)d_in[26];
    float* out = (float*)d_out;

    void *p;
    cudaGetSymbolAddress(&p, g_cat_hi);  uint16_t* cat_hi = (uint16_t*)p;
    cudaGetSymbolAddress(&p, g_cat_lo);  uint16_t* cat_lo = (uint16_t*)p;
    cudaGetSymbolAddress(&p, g_h);       float* h = (float*)p;
    cudaGetSymbolAddress(&p, g_xn_hi);   uint16_t* xn_hi = (uint16_t*)p;
    cudaGetSymbolAddress(&p, g_xn_lo);   uint16_t* xn_lo = (uint16_t*)p;
    cudaGetSymbolAddress(&p, g_qkv);     float* qkv = (float*)p;
    cudaGetSymbolAddress(&p, g_att_hi);  uint16_t* att_hi = (uint16_t*)p;
    cudaGetSymbolAddress(&p, g_att_lo);  uint16_t* att_lo = (uint16_t*)p;
    cudaGetSymbolAddress(&p, g_uf);      float* uf = (float*)p;
    cudaGetSymbolAddress(&p, g_u_hi);    uint16_t* u_hi = (uint16_t*)p;
    cudaGetSymbolAddress(&p, g_u_lo);    uint16_t* u_lo = (uint16_t*)p;
    cudaGetSymbolAddress(&p, g_w2p);     float* w2p = (float*)p;
    cudaGetSymbolAddress(&p, g_whi);     uint16_t* whi = (uint16_t*)p;
    cudaGetSymbolAddress(&p, g_wlo);     uint16_t* wlo = (uint16_t*)p;
    cudaGetSymbolAddress(&p, g_ropec);   float* ropec = (float*)p;
    cudaGetSymbolAddress(&p, g_ropes);   float* ropes = (float*)p;

    cudaFuncSetAttribute(attn_k, cudaFuncAttributeMaxDynamicSharedMemorySize, 131072);
    cudaFuncSetAttribute(tgemm_k, cudaFuncAttributeMaxDynamicSharedMemorySize, TG_DSMEM);

    detect_k<<<1, 1>>>((const int*)x);
    embed_k<<<NTOK, 192>>>(x, emb, reg_w, reg_b, br_w, br_b, sh_w, sh_b, cat_hi, cat_lo);
    padw2_k<<<1536, 256>>>(w2_w, w2p);
    ropetab_k<<<LSEQ, 32>>>(ropec, ropes);

    splitw_k<<<1024, 256>>>(inst_w, whi + OFF_INST, wlo + OFF_INST, CNT_INST);
    splitqkv_k<<<2048, 256>>>(qkv_w, whi + OFF_QKV, wlo + OFF_QKV);
    splitw_k<<<1024, 256>>>(out_w,  whi + OFF_OUT,  wlo + OFF_OUT,  CNT_OUT);
    splitw_k<<<2048, 256>>>(w1_w,   whi + OFF_W1,   wlo + OFF_W1,   CNT_W1);
    splitw_k<<<2048, 256>>>(w3_w,   whi + OFF_W3,   wlo + OFF_W3,   CNT_W3);
    splitw_k<<<2048, 256>>>(w2p,    whi + OFF_W2,   wlo + OFF_W2,   CNT_W2);

    // encoder: h = silu(cat) @ inst_w.T + inst_b
    tgemm_k<<<dim3(4, 64), 256, TG_DSMEM>>>(cat_hi, cat_lo, 768,
                                            whi + OFF_INST, wlo + OFF_INST, 768,
                                            inst_b, nullptr, nullptr,
                                            h, nullptr, nullptr, 512, 512, 768);
    lnsilu_k<<<NTOK, 128>>>(h, enc_ln_w, enc_ln_b);

    for (int l = 0; l < 3; l++) {
        rms_k<<<NTOK, 128>>>(h, n1_w + l * 512, xn_hi, xn_lo);
        tgemm_k<<<dim3(12, 64), 256, TG_DSMEM>>>(xn_hi, xn_lo, 512,
                                                 whi + OFF_QKV + (size_t)l * 1536 * 512,
                                                 wlo + OFF_QKV + (size_t)l * 1536 * 512, 512,
                                                 nullptr, nullptr, nullptr,
                                                 qkv, nullptr, nullptr, 1536, 1536, 512);
        attn_k<<<dim3(16, 8, 4), 256, 131072>>>(qkv, ropec, ropes, att_hi, att_lo);
        tgemm_k<<<dim3(4, 64), 256, TG_DSMEM>>>(att_hi, att_lo, 512,
                                                whi + OFF_OUT + (size_t)l * 512 * 512,
                                                wlo + OFF_OUT + (size_t)l * 512 * 512, 512,
                                                out_b + l * 512, h, nullptr,
                                                h, nullptr, nullptr, 512, 512, 512);
        rms_k<<<NTOK, 128>>>(h, n2_w + l * 512, xn_hi, xn_lo);
        tgemm_k<<<dim3(11, 64), 256, TG_DSMEM>>>(xn_hi, xn_lo, 512,
                                                 whi + OFF_W1 + (size_t)l * DFF * 512,
                                                 wlo + OFF_W1 + (size_t)l * DFF * 512, 512,
                                                 w1_b + l * DFF, nullptr, nullptr,
                                                 uf, nullptr, nullptr, DFFP, DFF, 512);
        tgemm_k<<<dim3(11, 64), 256, TG_DSMEM>>>(xn_hi, xn_lo, 512,
                                                 whi + OFF_W3 + (size_t)l * DFF * 512,
                                                 wlo + OFF_W3 + (size_t)l * DFF * 512, 512,
                                                 w3_b + l * DFF, nullptr, uf,
                                                 nullptr, u_hi, u_lo, DFFP, DFF, 512);
        tgemm_k<<<dim3(4, 64), 256, TG_DSMEM>>>(u_hi, u_lo, DFFP,
                                                whi + OFF_W2 + (size_t)l * 512 * DFFP,
                                                wlo + OFF_W2 + (size_t)l * 512 * DFFP, DFFP,
                                                w2_b + l * 512, h, nullptr,
                                                h, nullptr, nullptr, 512, 512, 1376);
    }

    head_k<<<NTOK, 256>>>(h, head_ln_w, head_ln_b, head_w, head_b, out);
}